// round 2
// baseline (speedup 1.0000x reference)
#include <cuda_runtime.h>
#include <math.h>

// MusicRNN: 2-layer LSTM (B=2048, T=256, I=88, H=64) + FC (O=13).
// Batch-partitioned persistent-per-layer kernels; CTA owns 16 batch elements,
// weights resident in SMEM, T=256 recurrence with zero inter-CTA comm.
// R1 changes: 512 threads/CTA (16 warps), duplicated x/h storage in SMEM so
// packed f32x2 FMA operands load directly (no dup MOVs).

namespace {
constexpr int B  = 2048;
constexpr int T  = 256;
constexpr int I  = 88;
constexpr int H  = 64;
constexpr int O  = 13;
constexpr int G4 = 4 * H;   // 256 gate columns
constexpr int BS = 16;      // batch elements per CTA
constexpr int SRS = 36;     // sX row stride in floats (2*BS duplicated + pad, even)
constexpr int PJ = 260;     // padded gate stride (multiple of 4, not of 32)
constexpr int NT = 512;     // threads per CTA
}

// ys1 scratch: [T][B][H] fp32 = 128 MB (static device array: allocation-free rule)
__device__ float g_ys1[(size_t)T * B * H];

typedef unsigned long long ull;

__device__ __forceinline__ ull pack2(float a, float b) {
    ull r; asm("mov.b64 %0, {%1, %2};" : "=l"(r) : "f"(a), "f"(b)); return r;
}
__device__ __forceinline__ void unpack2(ull v, float& a, float& b) {
    asm("mov.b64 {%0, %1}, %2;" : "=f"(a), "=f"(b) : "l"(v));
}
// packed dual fp32 FMA (sm_100+; ptxas never auto-fuses this)
__device__ __forceinline__ ull ffma2(ull a, ull b, ull c) {
    ull d; asm("fma.rn.f32x2 %0, %1, %2, %3;" : "=l"(d) : "l"(a), "l"(b), "l"(c));
    return d;
}

// Accurate activations from __expf (abs err ~1e-7); avoid MUFU.TANH coarseness.
__device__ __forceinline__ float fsig(float x) {
    return __fdividef(1.f, 1.f + __expf(-x));
}
__device__ __forceinline__ float ftanh(float x) {
    return __fdividef(2.f, 1.f + __expf(-2.f * x)) - 1.f;
}

template <int IN, bool IS_L1>
__global__ void __launch_bounds__(NT, 1) lstm_kernel(
    const float* __restrict__ xin,   // L1: x [B,T,IN]; L2: unused (reads g_ys1)
    const float* __restrict__ w_ih,  // [4H, IN]
    const float* __restrict__ w_hh,  // [4H, H]
    const float* __restrict__ b_ih,  // [4H]
    const float* __restrict__ b_hh,  // [4H]
    const float* __restrict__ fc_w,  // [O, H]   (L2 only)
    const float* __restrict__ fc_b,  // [O]      (L2 only)
    float* __restrict__ out)         // [B, O]   (L2 only)
{
    constexpr int K = IN + H;        // fused input+recurrent contraction dim
    extern __shared__ float sm[];
    float* sW    = sm;               // [K][PJ]   weights transposed (k-major)
    float* sX    = sW + K * PJ;      // [K][SRS]  x/h values DUPLICATED: (v,v) at 2b
    float* sG    = sX + K * SRS;     // [BS][PJ]  gate pre-activations
    float* sBias = sG + BS * PJ;     // [G4]

    const int tid = threadIdx.x;
    const int batch0 = blockIdx.x * BS;

    // ---- one-time: weights -> SMEM transposed so gate index is contiguous
    for (int idx = tid; idx < G4 * IN; idx += NT) {
        int j = idx / IN, k = idx - j * IN;
        sW[k * PJ + j] = w_ih[idx];
    }
    for (int idx = tid; idx < G4 * H; idx += NT) {
        int j = idx >> 6, k = idx & 63;
        sW[(IN + k) * PJ + j] = w_hh[idx];
    }
    if (tid < G4) sBias[tid] = b_ih[tid] + b_hh[tid];
    for (int idx = tid; idx < H * SRS; idx += NT) sX[IN * SRS + idx] = 0.f;  // h0=0
    __syncthreads();

    // Phase-B tile: 2 batch x 4 gates per thread
    const int jg = tid & 63;            // 64 gate groups
    const int bg = tid >> 6;            // 8 batch groups
    const int j0 = jg << 2;
    const int b0 = bg << 1;
    // Phase-C ownership: one h index, 2 batch elements
    const int hC = tid & 63;
    const int bC = (tid >> 6) << 1;

    const float4 bv = *(const float4*)(sBias + j0);
    const ull bias01 = pack2(bv.x, bv.y);
    const ull bias23 = pack2(bv.z, bv.w);

    float c_reg[2] = {0.f, 0.f};

    for (int t = 0; t < T; ++t) {
        // ---- Phase A: stage x_t duplicated into sX rows [0, IN)
        if constexpr (IS_L1) {
            const float* xb = xin + (size_t)t * IN + (size_t)batch0 * T * IN;
            for (int idx = tid; idx < BS * IN; idx += NT) {
                int b = idx / IN, k = idx - b * IN;
                float v = xb[(size_t)b * T * IN + k];
                *(ull*)(sX + k * SRS + 2 * b) = pack2(v, v);
            }
        } else {
            const float* yb = g_ys1 + ((size_t)t * B + batch0) * H;
            for (int idx = tid; idx < BS * IN; idx += NT) {
                int b = idx >> 6, k = idx & 63;
                float v = yb[(b << 6) + k];
                *(ull*)(sX + k * SRS + 2 * b) = pack2(v, v);
            }
        }
        __syncthreads();  // orders A-writes AND prev-step h-writes before GEMM

        // ---- Phase B: gates[b][j] = sum_k xh[k][b] * W[k][j] + bias
        ull a00 = bias01, a01 = bias23;   // batch b0,   gates j0..j0+3
        ull a10 = bias01, a11 = bias23;   // batch b0+1
        const float* pw = sW + j0;
        const float* px = sX + 2 * b0;
        #pragma unroll 8
        for (int k = 0; k < K; ++k) {
            const float4 w = *(const float4*)(pw + k * PJ);      // per-thread pair regs
            const ull x0 = *(const ull*)(px + k * SRS);          // (x_b0 , x_b0 )  bcast
            const ull x1 = *(const ull*)(px + k * SRS + 2);      // (x_b0+1,x_b0+1) bcast
            const ull w01 = pack2(w.x, w.y), w23 = pack2(w.z, w.w);
            a00 = ffma2(x0, w01, a00); a01 = ffma2(x0, w23, a01);
            a10 = ffma2(x1, w01, a10); a11 = ffma2(x1, w23, a11);
        }
        {
            float4 r;
            unpack2(a00, r.x, r.y); unpack2(a01, r.z, r.w);
            *(float4*)(sG + (b0 + 0) * PJ + j0) = r;
            unpack2(a10, r.x, r.y); unpack2(a11, r.z, r.w);
            *(float4*)(sG + (b0 + 1) * PJ + j0) = r;
        }
        __syncthreads();

        // ---- Phase C: LSTM cell elementwise; h feeds back (duplicated) into sX
        #pragma unroll
        for (int q = 0; q < 2; ++q) {
            const int b = bC + q;
            float gi = sG[b * PJ + hC];
            float gf = sG[b * PJ + 64 + hC];
            float gg = sG[b * PJ + 128 + hC];
            float go = sG[b * PJ + 192 + hC];
            gi = fsig(gi); gf = fsig(gf); go = fsig(go);
            gg = ftanh(gg);
            const float c = gf * c_reg[q] + gi * gg;
            c_reg[q] = c;
            const float hv = go * ftanh(c);
            *(ull*)(sX + (IN + hC) * SRS + 2 * b) = pack2(hv, hv);
            if constexpr (IS_L1)
                g_ys1[((size_t)t * B + (batch0 + b)) * H + hC] = hv;
        }
        // C-writes ordered before next B by the sync after next Phase A
    }

    // ---- layer2 epilogue: fused FC head out = h_last @ fc_w^T + fc_b
    if constexpr (!IS_L1) {
        __syncthreads();
        for (int idx = tid; idx < BS * O; idx += NT) {
            int b = idx / O, o = idx - (idx / O) * O;
            float s = fc_b[o];
            #pragma unroll
            for (int h = 0; h < H; ++h)
                s += sX[(IN + h) * SRS + 2 * b] * fc_w[o * H + h];
            out[(batch0 + b) * O + o] = s;
        }
    }
}

extern "C" void kernel_launch(void* const* d_in, const int* in_sizes, int n_in,
                              void* d_out, int out_size) {
    const float* x     = (const float*)d_in[0];
    const float* w_ih0 = (const float*)d_in[1];
    const float* w_hh0 = (const float*)d_in[2];
    const float* b_ih0 = (const float*)d_in[3];
    const float* b_hh0 = (const float*)d_in[4];
    const float* w_ih1 = (const float*)d_in[5];
    const float* w_hh1 = (const float*)d_in[6];
    const float* b_ih1 = (const float*)d_in[7];
    const float* b_hh1 = (const float*)d_in[8];
    const float* fc_w  = (const float*)d_in[9];
    const float* fc_b  = (const float*)d_in[10];
    float* out = (float*)d_out;

    constexpr int K1 = I + H;   // 152
    constexpr int K2 = H + H;   // 128
    const size_t sm1 = (size_t)(K1 * PJ + K1 * SRS + BS * PJ + G4) * sizeof(float); // ~198 KB
    const size_t sm2 = (size_t)(K2 * PJ + K2 * SRS + BS * PJ + G4) * sizeof(float); // ~170 KB

    cudaFuncSetAttribute(lstm_kernel<I, true>,
                         cudaFuncAttributeMaxDynamicSharedMemorySize, (int)sm1);
    cudaFuncSetAttribute(lstm_kernel<H, false>,
                         cudaFuncAttributeMaxDynamicSharedMemorySize, (int)sm2);

    lstm_kernel<I, true><<<B / BS, NT, sm1>>>(
        x, w_ih0, w_hh0, b_ih0, b_hh0, nullptr, nullptr, nullptr);
    lstm_kernel<H, false><<<B / BS, NT, sm2>>>(
        nullptr, w_ih1, w_hh1, b_ih1, b_hh1, fc_w, fc_b, out);
}

// round 3
// speedup vs baseline: 1.2582x; 1.2582x over previous
#include <cuda_runtime.h>
#include <math.h>

// MusicRNN: 2-layer LSTM (B=2048, T=256, I=88, H=64) + FC (O=13).
// R2 structure: 4 kernels.
//  k1: pre = x @ W_ih0^T + (b_ih0+b_hh0)       (parallel GEMM over all T)
//  k2: L1 recurrence, K=64 only -> ys1
//  k3: pre = ys1 @ W_ih1^T + (b_ih1+b_hh1)     (parallel GEMM, reuses pre buf)
//  k4: L2 recurrence + fused FC head -> out
// Recurrence: CTA owns 16 batch elems, W_hh in SMEM, FFMA2 pairs BATCHES so
// x operands load as ull directly (no dup movs); W needs only 2 movs/k.

namespace {
constexpr int B = 2048, T = 256, I = 88, H = 64, O = 13, G4 = 256;
constexpr int NP = 260, MP = 132;          // GEMM smem strides
constexpr int WP = 258, XP = 20, GP = 18;  // recurrence smem strides
}

// scratch (static __device__: allocation-free rule). pre reused by both layers.
__device__ float g_pre[(size_t)T * B * G4];   // 512 MB
__device__ float g_ys1[(size_t)T * B * H];    // 128 MB

typedef unsigned long long ull;

__device__ __forceinline__ ull pack2(float a, float b) {
    ull r; asm("mov.b64 %0, {%1, %2};" : "=l"(r) : "f"(a), "f"(b)); return r;
}
// packed dual fp32 FMA (sm_100+)
__device__ __forceinline__ ull ffma2(ull a, ull b, ull c) {
    ull d; asm("fma.rn.f32x2 %0, %1, %2, %3;" : "=l"(d) : "l"(a), "l"(b), "l"(c));
    return d;
}
__device__ __forceinline__ float fsig(float x) {
    return __fdividef(1.f, 1.f + __expf(-x));
}
__device__ __forceinline__ float ftanh(float x) {
    return __fdividef(2.f, 1.f + __expf(-2.f * x)) - 1.f;
}

// ---------------- input-projection GEMM: pre[t][b][256] = src_row . W^T + bias
// CTA tile: 128 batch rows (fixed t) x all 256 gates. Thread: 8m x 16n.
// FFMA2 pairs the n (gate) dim: w pairs load directly, x is duplicated by movs.
template <int KK, bool FROMX>
__global__ void __launch_bounds__(256, 1) gemm_pre(
    const float* __restrict__ src,   // FROMX: x [B][T][KK]; else unused (g_ys1)
    const float* __restrict__ w,     // [256][KK]
    const float* __restrict__ bia,
    const float* __restrict__ bib)
{
    extern __shared__ float sm[];
    float* sW = sm;               // [KK][NP]
    float* sX = sW + KK * NP;     // [KK][MP]
    float* sB = sX + KK * MP;     // [256]
    const int tid = threadIdx.x;
    const int b0 = blockIdx.x * 128, t = blockIdx.y;

    for (int idx = tid; idx < G4 * KK; idx += 256) {
        int j = idx / KK, k = idx - j * KK;
        sW[k * NP + j] = w[idx];
    }
    sB[tid] = bia[tid] + bib[tid];
    for (int idx = tid; idx < 128 * KK; idx += 256) {
        int m = idx / KK, k = idx - m * KK;
        const float* srow = FROMX ? src + ((size_t)(b0 + m) * T + t) * KK
                                  : g_ys1 + ((size_t)t * B + b0 + m) * KK;
        sX[k * MP + m] = srow[k];
    }
    __syncthreads();

    const int m0 = (tid >> 4) * 8;
    const int n0 = (tid & 15) * 16;

    ull acc[8][8];
    #pragma unroll
    for (int np = 0; np < 8; ++np) {
        const ull bp = *(const ull*)(sB + n0 + 2 * np);
        #pragma unroll
        for (int m = 0; m < 8; ++m) acc[m][np] = bp;
    }

    const float* pw = sW + n0;
    const float* px = sX + m0;
    #pragma unroll 4
    for (int k = 0; k < KK; ++k) {
        const ulonglong2 wA = *(const ulonglong2*)(pw + (size_t)k * NP);
        const ulonglong2 wB = *(const ulonglong2*)(pw + (size_t)k * NP + 4);
        const ulonglong2 wC = *(const ulonglong2*)(pw + (size_t)k * NP + 8);
        const ulonglong2 wD = *(const ulonglong2*)(pw + (size_t)k * NP + 12);
        const ull wp[8] = {wA.x, wA.y, wB.x, wB.y, wC.x, wC.y, wD.x, wD.y};
        const float4 xa = *(const float4*)(px + (size_t)k * MP);
        const float4 xb = *(const float4*)(px + (size_t)k * MP + 4);
        ull xm[8];
        xm[0] = pack2(xa.x, xa.x); xm[1] = pack2(xa.y, xa.y);
        xm[2] = pack2(xa.z, xa.z); xm[3] = pack2(xa.w, xa.w);
        xm[4] = pack2(xb.x, xb.x); xm[5] = pack2(xb.y, xb.y);
        xm[6] = pack2(xb.z, xb.z); xm[7] = pack2(xb.w, xb.w);
        #pragma unroll
        for (int m = 0; m < 8; ++m)
            #pragma unroll
            for (int np = 0; np < 8; ++np)
                acc[m][np] = ffma2(xm[m], wp[np], acc[m][np]);
    }

    float* dst = g_pre + ((size_t)t * B + b0 + m0) * G4 + n0;
    #pragma unroll
    for (int m = 0; m < 8; ++m)
        #pragma unroll
        for (int np = 0; np < 8; ++np)
            *(ull*)(dst + (size_t)m * G4 + 2 * np) = acc[m][np];
}

// ---------------- recurrence: gates = pre[t] + h @ W_hh^T ; LSTM cell
// CTA = 16 batch. Phase B: 256 thr, tile 8b x 2g, FFMA2 pairs batches.
template <bool ISL1>
__global__ void __launch_bounds__(256, 1) lstm_rec(
    const float* __restrict__ w_hh,   // [256][64]
    const float* __restrict__ fc_w,   // [O][H]  (L2 only)
    const float* __restrict__ fc_b,   // [O]     (L2 only)
    float* __restrict__ out)          // [B][O]  (L2 only)
{
    extern __shared__ float sm[];
    float* sW = sm;               // [64][WP]  W_hh transposed
    float* sX = sW + 64 * WP;     // [64][XP]  h values [h][b]
    float* sG = sX + 64 * XP;     // [256][GP] recurrent gate partials [j][b]
    const int tid = threadIdx.x;
    const int batch0 = blockIdx.x * 16;

    for (int idx = tid; idx < G4 * H; idx += 256) {
        int j = idx >> 6, k = idx & 63;
        sW[k * WP + j] = w_hh[idx];
    }
    for (int idx = tid; idx < 64 * XP; idx += 256) sX[idx] = 0.f;  // h0 = 0
    __syncthreads();

    const int jg = tid & 127, bg = tid >> 7;      // B-phase roles
    const int hC = tid & 63,  bC = (tid >> 6) * 4; // C-phase roles

    float c_reg[4] = {0.f, 0.f, 0.f, 0.f};
    const float* pw = sW + 2 * jg;
    const float* px = sX + bg * 8;

    for (int t = 0; t < T; ++t) {
        // prefetch additive input pre[t] (consumed in phase C; hidden by B)
        const float* pt = g_pre + ((size_t)t * B + batch0) * G4;
        float pv[4][4];
        #pragma unroll
        for (int q = 0; q < 4; ++q)
            #pragma unroll
            for (int g = 0; g < 4; ++g)
                pv[q][g] = pt[(bC + q) * G4 + g * 64 + hC];

        // phase B: sG[j][b] = sum_k h[k][b] * W[k][j]
        ull a00 = 0, a01 = 0, a10 = 0, a11 = 0, a20 = 0, a21 = 0, a30 = 0, a31 = 0;
        #pragma unroll 8
        for (int k = 0; k < 64; ++k) {
            const float2 wv = *(const float2*)(pw + k * WP);
            const ull w0 = pack2(wv.x, wv.x);
            const ull w1 = pack2(wv.y, wv.y);
            const ulonglong2 xA = *(const ulonglong2*)(px + k * XP);
            const ulonglong2 xB = *(const ulonglong2*)(px + k * XP + 4);
            a00 = ffma2(xA.x, w0, a00); a01 = ffma2(xA.x, w1, a01);
            a10 = ffma2(xA.y, w0, a10); a11 = ffma2(xA.y, w1, a11);
            a20 = ffma2(xB.x, w0, a20); a21 = ffma2(xB.x, w1, a21);
            a30 = ffma2(xB.y, w0, a31 - a31 + a20 * 0 + a30); a31 = ffma2(xB.y, w1, a31);
        }
        {
            float* g0 = sG + (2 * jg) * GP + bg * 8;
            float* g1 = sG + (2 * jg + 1) * GP + bg * 8;
            *(ull*)(g0)     = a00; *(ull*)(g0 + 2) = a10;
            *(ull*)(g0 + 4) = a20; *(ull*)(g0 + 6) = a30;
            *(ull*)(g1)     = a01; *(ull*)(g1 + 2) = a11;
            *(ull*)(g1 + 4) = a21; *(ull*)(g1 + 6) = a31;
        }
        __syncthreads();

        // phase C: LSTM cell; h feeds back into sX
        #pragma unroll
        for (int q = 0; q < 4; ++q) {
            const int b = bC + q;
            float gi = sG[hC * GP + b]         + pv[q][0];
            float gf = sG[(64 + hC) * GP + b]  + pv[q][1];
            float gg = sG[(128 + hC) * GP + b] + pv[q][2];
            float go = sG[(192 + hC) * GP + b] + pv[q][3];
            gi = fsig(gi); gf = fsig(gf); go = fsig(go); gg = ftanh(gg);
            const float c = gf * c_reg[q] + gi * gg;
            c_reg[q] = c;
            const float hv = go * ftanh(c);
            sX[hC * XP + b] = hv;
            if (ISL1)
                g_ys1[((size_t)t * B + batch0 + b) * H + hC] = hv;
        }
        __syncthreads();
    }

    if (!ISL1) {
        for (int idx = tid; idx < 16 * O; idx += 256) {
            int b = idx / O, o = idx - (idx / O) * O;
            float s = fc_b[o];
            #pragma unroll
            for (int h = 0; h < H; ++h)
                s += sX[h * XP + b] * fc_w[o * H + h];
            out[(batch0 + b) * O + o] = s;
        }
    }
}

extern "C" void kernel_launch(void* const* d_in, const int* in_sizes, int n_in,
                              void* d_out, int out_size) {
    const float* x     = (const float*)d_in[0];
    const float* w_ih0 = (const float*)d_in[1];
    const float* w_hh0 = (const float*)d_in[2];
    const float* b_ih0 = (const float*)d_in[3];
    const float* b_hh0 = (const float*)d_in[4];
    const float* w_ih1 = (const float*)d_in[5];
    const float* w_hh1 = (const float*)d_in[6];
    const float* b_ih1 = (const float*)d_in[7];
    const float* b_hh1 = (const float*)d_in[8];
    const float* fc_w  = (const float*)d_in[9];
    const float* fc_b  = (const float*)d_in[10];
    float* out = (float*)d_out;

    const size_t smG1 = (size_t)(I * NP + I * MP + G4) * sizeof(float);  // ~136 KB
    const size_t smG2 = (size_t)(H * NP + H * MP + G4) * sizeof(float);  // ~99 KB
    const size_t smR  = (size_t)(64 * WP + 64 * XP + G4 * GP) * sizeof(float); // ~88 KB

    cudaFuncSetAttribute(gemm_pre<I, true>,
                         cudaFuncAttributeMaxDynamicSharedMemorySize, (int)smG1);
    cudaFuncSetAttribute(gemm_pre<H, false>,
                         cudaFuncAttributeMaxDynamicSharedMemorySize, (int)smG2);
    cudaFuncSetAttribute(lstm_rec<true>,
                         cudaFuncAttributeMaxDynamicSharedMemorySize, (int)smR);
    cudaFuncSetAttribute(lstm_rec<false>,
                         cudaFuncAttributeMaxDynamicSharedMemorySize, (int)smR);

    dim3 gG(B / 128, T);
    gemm_pre<I, true><<<gG, 256, smG1>>>(x, w_ih0, b_ih0, b_hh0);
    lstm_rec<true><<<B / 16, 256, smR>>>(w_hh0, nullptr, nullptr, nullptr);
    gemm_pre<H, false><<<gG, 256, smG2>>>(nullptr, w_ih1, b_ih1, b_hh1);
    lstm_rec<false><<<B / 16, 256, smR>>>(w_hh1, fc_w, fc_b, out);
}

// round 6
// speedup vs baseline: 2.3661x; 1.8806x over previous
#include <cuda_runtime.h>
#include <cuda_bf16.h>
#include <cstdint>
#include <math.h>

// MusicRNN: 2-layer LSTM (B=2048, T=256, I=88, H=64) + FC (O=13).
// R5: tcgen05 is unusable (harness compiles PTX at .target sm_103, no 'a'
// suffix -> arch-accelerated instrs rejected). Pre-activation GEMMs now use
// baseline-PTX warp MMA (mma.sync.m16n8k16 bf16, HMMA) with split-bf16
// (hi+lo) operands: D = Ah*Wh + Al*Wh + Ah*Wl, fp32 accumulators.
// Bias folded in as an extra K column. Recurrence = proven R2 design.

namespace {
constexpr int B = 2048, T = 256, I = 88, H = 64, O = 13, G4 = 256;
constexpr int WP = 258, XP = 20, GP = 18;   // recurrence smem strides
constexpr int NTILES = T * (B / 128);       // 4096 tiles of 128 rows
}

// scratch (static __device__: allocation-free rule)
__device__ float g_pre[(size_t)T * B * G4];   // 512 MB
__device__ float g_ys1[(size_t)T * B * H];    // 128 MB

typedef unsigned long long ull;

// ---------------- warp-MMA bf16 (baseline PTX, works on .target sm_103) ----
__device__ __forceinline__ void mma16816(float* c, const uint32_t* a,
                                         uint32_t b0, uint32_t b1) {
    asm volatile(
        "mma.sync.aligned.m16n8k16.row.col.f32.bf16.bf16.f32 "
        "{%0,%1,%2,%3}, {%4,%5,%6,%7}, {%8,%9}, {%0,%1,%2,%3};"
        : "+f"(c[0]), "+f"(c[1]), "+f"(c[2]), "+f"(c[3])
        : "r"(a[0]), "r"(a[1]), "r"(a[2]), "r"(a[3]), "r"(b0), "r"(b1));
}
__device__ __forceinline__ uint32_t ld32bf(const __nv_bfloat16* p) {
    return *(const uint32_t*)p;
}
__device__ __forceinline__ void split_bf16(float v, __nv_bfloat16& h,
                                           __nv_bfloat16& l) {
    h = __float2bfloat16(v);
    l = __float2bfloat16(v - __bfloat162float(h));
}

// ---------------- pre-GEMM: g_pre[t][b][256] = src_row . W^T + bias --------
// Persistent CTAs (grid=148) x 512 thr. W (split hi/lo, bias col) resident in
// SMEM. Per tile: stage A (128 rows, fp32 -> split bf16), 16 warps compute
// 32x64 each (2m x 8n x KP/16 k-steps x 3 split terms), store fp32 to g_pre.
// KDATA: real K (88 or 64); bias col at KDATA; KP: padded to mult of 16.
template <int KDATA, int KP, bool FROMX>
__global__ void __launch_bounds__(512, 1) gemm_pre_mma(
    const float* __restrict__ src,   // FROMX: x [B][T][KDATA]; else g_ys1
    const float* __restrict__ w,     // [256][KDATA]
    const float* __restrict__ bia, const float* __restrict__ bib)
{
    constexpr int SA = KP + 8;   // smem row stride in halves (conflict-free)
    extern __shared__ __nv_bfloat16 smh[];
    __nv_bfloat16* sWH = smh;                 // [256][SA]
    __nv_bfloat16* sWL = sWH + 256 * SA;      // [256][SA]
    __nv_bfloat16* sAH = sWL + 256 * SA;      // [128][SA]
    __nv_bfloat16* sAL = sAH + 128 * SA;      // [128][SA]

    const int tid = threadIdx.x;

    // zero all smem once (pads + unwritten cols stay zero forever)
    for (int i = tid; i < 768 * SA / 2; i += 512)
        ((uint32_t*)smh)[i] = 0u;
    __syncthreads();

    // W -> split bf16; bias folded as column KDATA of W; A gets ones col.
    for (int idx = tid; idx < 256 * KDATA; idx += 512) {
        int j = idx / KDATA, k = idx - j * KDATA;
        __nv_bfloat16 h, l;
        split_bf16(w[idx], h, l);
        sWH[j * SA + k] = h;
        sWL[j * SA + k] = l;
    }
    if (tid < 256) {
        __nv_bfloat16 h, l;
        split_bf16(bia[tid] + bib[tid], h, l);
        sWH[tid * SA + KDATA] = h;
        sWL[tid * SA + KDATA] = l;
    }
    if (tid < 128)
        sAH[tid * SA + KDATA] = __float2bfloat16(1.0f);  // lo stays 0

    const int lane = tid & 31, wid = tid >> 5;
    const int g = lane >> 2, tg = lane & 3;
    const int wRow = (wid & 3) * 32;     // 4 row groups x 32
    const int wCol = (wid >> 2) * 64;    // 4 col groups x 64

    for (int tile = blockIdx.x; tile < NTILES; tile += gridDim.x) {
        const int t = tile >> 4, b0 = (tile & 15) << 7;

        // ---- stage A tile: fp32 -> hi/lo bf16
        __syncthreads();   // protect prior iteration's frag reads
        for (int idx = tid; idx < 128 * (KDATA / 2); idx += 512) {
            int m = idx / (KDATA / 2), kp = idx - m * (KDATA / 2);
            const float* rp = FROMX
                ? src + ((size_t)(b0 + m) * T + t) * KDATA
                : g_ys1 + ((size_t)t * B + (b0 + m)) * KDATA;
            float2 v = *(const float2*)(rp + 2 * kp);
            __nv_bfloat16 h0, l0, h1, l1;
            split_bf16(v.x, h0, l0);
            split_bf16(v.y, h1, l1);
            sAH[m * SA + 2 * kp] = h0; sAH[m * SA + 2 * kp + 1] = h1;
            sAL[m * SA + 2 * kp] = l0; sAL[m * SA + 2 * kp + 1] = l1;
        }
        __syncthreads();

        // ---- warp MMA: 32x64 per warp
        float acc[2][8][4] = {};
        #pragma unroll
        for (int kk = 0; kk < KP / 16; ++kk) {
            uint32_t ah[2][4], al[2][4];
            #pragma unroll
            for (int f = 0; f < 2; ++f) {
                const int base = (wRow + f * 16 + g) * SA + kk * 16 + tg * 2;
                ah[f][0] = ld32bf(sAH + base);
                ah[f][1] = ld32bf(sAH + base + 8 * SA);
                ah[f][2] = ld32bf(sAH + base + 8);
                ah[f][3] = ld32bf(sAH + base + 8 * SA + 8);
                al[f][0] = ld32bf(sAL + base);
                al[f][1] = ld32bf(sAL + base + 8 * SA);
                al[f][2] = ld32bf(sAL + base + 8);
                al[f][3] = ld32bf(sAL + base + 8 * SA + 8);
            }
            #pragma unroll
            for (int n = 0; n < 8; ++n) {
                const int bbase = (wCol + n * 8 + g) * SA + kk * 16 + tg * 2;
                const uint32_t bh0 = ld32bf(sWH + bbase);
                const uint32_t bh1 = ld32bf(sWH + bbase + 8);
                const uint32_t bl0 = ld32bf(sWL + bbase);
                const uint32_t bl1 = ld32bf(sWL + bbase + 8);
                #pragma unroll
                for (int f = 0; f < 2; ++f) {
                    mma16816(acc[f][n], ah[f], bh0, bh1);   // Ah*Wh
                    mma16816(acc[f][n], al[f], bh0, bh1);   // Al*Wh
                    mma16816(acc[f][n], ah[f], bl0, bl1);   // Ah*Wl
                }
            }
        }

        // ---- epilogue: fp32 accum -> g_pre[t][b][gate]
        float* orow = g_pre + ((size_t)t * B + b0) * G4;
        #pragma unroll
        for (int f = 0; f < 2; ++f) {
            const int r0 = wRow + f * 16 + g;
            #pragma unroll
            for (int n = 0; n < 8; ++n) {
                const int col = wCol + n * 8 + tg * 2;
                float2 v0 = make_float2(acc[f][n][0], acc[f][n][1]);
                float2 v1 = make_float2(acc[f][n][2], acc[f][n][3]);
                *(float2*)(orow + (size_t)r0 * G4 + col) = v0;
                *(float2*)(orow + (size_t)(r0 + 8) * G4 + col) = v1;
            }
        }
    }
}

// ---------------- recurrence (unchanged, proven R2 design) ----------------
__device__ __forceinline__ ull pack2(float a, float b) {
    ull r; asm("mov.b64 %0, {%1, %2};" : "=l"(r) : "f"(a), "f"(b)); return r;
}
__device__ __forceinline__ ull ffma2(ull a, ull b, ull c) {
    ull d; asm("fma.rn.f32x2 %0, %1, %2, %3;" : "=l"(d) : "l"(a), "l"(b), "l"(c));
    return d;
}
__device__ __forceinline__ float fsig(float x) {
    return __fdividef(1.f, 1.f + __expf(-x));
}
__device__ __forceinline__ float ftanh(float x) {
    return __fdividef(2.f, 1.f + __expf(-2.f * x)) - 1.f;
}

template <bool ISL1>
__global__ void __launch_bounds__(256, 1) lstm_rec(
    const float* __restrict__ w_hh,   // [256][64]
    const float* __restrict__ fc_w,   // [O][H]  (L2 only)
    const float* __restrict__ fc_b,   // [O]     (L2 only)
    float* __restrict__ out)          // [B][O]  (L2 only)
{
    extern __shared__ float sm[];
    float* sW = sm;               // [64][WP]  W_hh transposed
    float* sX = sW + 64 * WP;     // [64][XP]  h values [h][b]
    float* sG = sX + 64 * XP;     // [256][GP] recurrent gate partials [j][b]
    const int tid = threadIdx.x;
    const int batch0 = blockIdx.x * 16;

    for (int idx = tid; idx < G4 * H; idx += 256) {
        int j = idx >> 6, k = idx & 63;
        sW[k * WP + j] = w_hh[idx];
    }
    for (int idx = tid; idx < 64 * XP; idx += 256) sX[idx] = 0.f;  // h0 = 0
    __syncthreads();

    const int jg = tid & 127, bg = tid >> 7;       // B-phase roles
    const int hC = tid & 63,  bC = (tid >> 6) * 4; // C-phase roles

    float c_reg[4] = {0.f, 0.f, 0.f, 0.f};
    const float* pw = sW + 2 * jg;
    const float* px = sX + bg * 8;

    for (int t = 0; t < T; ++t) {
        const float* pt = g_pre + ((size_t)t * B + batch0) * G4;
        float pv[4][4];
        #pragma unroll
        for (int q = 0; q < 4; ++q)
            #pragma unroll
            for (int g = 0; g < 4; ++g)
                pv[q][g] = pt[(bC + q) * G4 + g * 64 + hC];

        ull a00 = 0, a01 = 0, a10 = 0, a11 = 0, a20 = 0, a21 = 0, a30 = 0, a31 = 0;
        #pragma unroll 8
        for (int k = 0; k < 64; ++k) {
            const float2 wv = *(const float2*)(pw + k * WP);
            const ull w0 = pack2(wv.x, wv.x);
            const ull w1 = pack2(wv.y, wv.y);
            const ulonglong2 xA = *(const ulonglong2*)(px + k * XP);
            const ulonglong2 xB = *(const ulonglong2*)(px + k * XP + 4);
            a00 = ffma2(xA.x, w0, a00); a01 = ffma2(xA.x, w1, a01);
            a10 = ffma2(xA.y, w0, a10); a11 = ffma2(xA.y, w1, a11);
            a20 = ffma2(xB.x, w0, a20); a21 = ffma2(xB.x, w1, a21);
            a30 = ffma2(xB.y, w0, a30); a31 = ffma2(xB.y, w1, a31);
        }
        {
            float* g0 = sG + (2 * jg) * GP + bg * 8;
            float* g1 = sG + (2 * jg + 1) * GP + bg * 8;
            *(ull*)(g0)     = a00; *(ull*)(g0 + 2) = a10;
            *(ull*)(g0 + 4) = a20; *(ull*)(g0 + 6) = a30;
            *(ull*)(g1)     = a01; *(ull*)(g1 + 2) = a11;
            *(ull*)(g1 + 4) = a21; *(ull*)(g1 + 6) = a31;
        }
        __syncthreads();

        #pragma unroll
        for (int q = 0; q < 4; ++q) {
            const int b = bC + q;
            float gi = sG[hC * GP + b]         + pv[q][0];
            float gf = sG[(64 + hC) * GP + b]  + pv[q][1];
            float gg = sG[(128 + hC) * GP + b] + pv[q][2];
            float go = sG[(192 + hC) * GP + b] + pv[q][3];
            gi = fsig(gi); gf = fsig(gf); go = fsig(go); gg = ftanh(gg);
            const float c = gf * c_reg[q] + gi * gg;
            c_reg[q] = c;
            const float hv = go * ftanh(c);
            sX[hC * XP + b] = hv;
            if (ISL1)
                g_ys1[((size_t)t * B + batch0 + b) * H + hC] = hv;
        }
        __syncthreads();
    }

    if (!ISL1) {
        for (int idx = tid; idx < 16 * O; idx += 256) {
            int b = idx / O, o = idx - (idx / O) * O;
            float s = fc_b[o];
            #pragma unroll
            for (int h = 0; h < H; ++h)
                s += sX[h * XP + b] * fc_w[o * H + h];
            out[(batch0 + b) * O + o] = s;
        }
    }
}

extern "C" void kernel_launch(void* const* d_in, const int* in_sizes, int n_in,
                              void* d_out, int out_size) {
    const float* x     = (const float*)d_in[0];
    const float* w_ih0 = (const float*)d_in[1];
    const float* w_hh0 = (const float*)d_in[2];
    const float* b_ih0 = (const float*)d_in[3];
    const float* b_hh0 = (const float*)d_in[4];
    const float* w_ih1 = (const float*)d_in[5];
    const float* w_hh1 = (const float*)d_in[6];
    const float* b_ih1 = (const float*)d_in[7];
    const float* b_hh1 = (const float*)d_in[8];
    const float* fc_w  = (const float*)d_in[9];
    const float* fc_b  = (const float*)d_in[10];
    float* out = (float*)d_out;

    // L1: KDATA=88, K=89 -> KP=96, SA=104. L2: KDATA=64, K=65 -> KP=80, SA=88.
    const int smG1 = 768 * (96 + 8) * 2;    // 159744 B
    const int smG2 = 768 * (80 + 8) * 2;    // 135168 B
    const size_t smR = (size_t)(64 * WP + 64 * XP + G4 * GP) * sizeof(float);

    cudaFuncSetAttribute(gemm_pre_mma<88, 96, true>,
                         cudaFuncAttributeMaxDynamicSharedMemorySize, smG1);
    cudaFuncSetAttribute(gemm_pre_mma<64, 80, false>,
                         cudaFuncAttributeMaxDynamicSharedMemorySize, smG2);
    cudaFuncSetAttribute(lstm_rec<true>,
                         cudaFuncAttributeMaxDynamicSharedMemorySize, (int)smR);
    cudaFuncSetAttribute(lstm_rec<false>,
                         cudaFuncAttributeMaxDynamicSharedMemorySize, (int)smR);

    gemm_pre_mma<88, 96, true><<<148, 512, smG1>>>(x, w_ih0, b_ih0, b_hh0);
    lstm_rec<true><<<B / 16, 256, smR>>>(w_hh0, nullptr, nullptr, nullptr);
    gemm_pre_mma<64, 80, false><<<148, 512, smG2>>>(nullptr, w_ih1, b_ih1, b_hh1);
    lstm_rec<false><<<B / 16, 256, smR>>>(w_hh1, fc_w, fc_b, out);
}

// round 7
// speedup vs baseline: 3.7854x; 1.5998x over previous
#include <cuda_runtime.h>
#include <cuda_bf16.h>
#include <cstdint>
#include <math.h>

// MusicRNN: 2-layer LSTM (B=2048, T=256, I=88, H=64) + FC (O=13).
// R6: recurrence moved to HMMA (mma.sync.m16n8k16 bf16, baseline PTX).
// Orientation gates^T = W_hh @ h^T so A(=W_hh) fragments are STATIC in
// registers (split hi/lo) for all 256 steps; per step only h (16x64) moves.
// Same 3-term split-bf16 precision scheme as the (passing) R5 GEMMs.
// Pre-activation GEMMs unchanged from R5.

namespace {
constexpr int B = 2048, T = 256, I = 88, H = 64, O = 13, G4 = 256;
constexpr int NTILES = T * (B / 128);       // 4096 tiles of 128 rows
constexpr int HBS = 24;                      // hB row stride (words) - cf reads
constexpr int GS  = 22;                      // sGate row stride (floats)
}

// scratch (static __device__: allocation-free rule)
__device__ float g_pre[(size_t)T * B * G4];   // 512 MB
__device__ float g_ys1[(size_t)T * B * H];    // 128 MB

typedef unsigned long long ull;

// ---------------- warp-MMA bf16 (baseline PTX, works on .target sm_103) ----
__device__ __forceinline__ void mma16816(float* c, const uint32_t* a,
                                         uint32_t b0, uint32_t b1) {
    asm volatile(
        "mma.sync.aligned.m16n8k16.row.col.f32.bf16.bf16.f32 "
        "{%0,%1,%2,%3}, {%4,%5,%6,%7}, {%8,%9}, {%0,%1,%2,%3};"
        : "+f"(c[0]), "+f"(c[1]), "+f"(c[2]), "+f"(c[3])
        : "r"(a[0]), "r"(a[1]), "r"(a[2]), "r"(a[3]), "r"(b0), "r"(b1));
}
__device__ __forceinline__ uint32_t ld32bf(const __nv_bfloat16* p) {
    return *(const uint32_t*)p;
}
__device__ __forceinline__ void split_bf16(float v, __nv_bfloat16& h,
                                           __nv_bfloat16& l) {
    h = __float2bfloat16(v);
    l = __float2bfloat16(v - __bfloat162float(h));
}
__device__ __forceinline__ uint32_t packbf(__nv_bfloat16 lo, __nv_bfloat16 hi) {
    return (uint32_t)__bfloat16_as_ushort(lo)
         | ((uint32_t)__bfloat16_as_ushort(hi) << 16);
}
__device__ __forceinline__ float fsig(float x) {
    return __fdividef(1.f, 1.f + __expf(-x));
}
__device__ __forceinline__ float ftanh(float x) {
    return __fdividef(2.f, 1.f + __expf(-2.f * x)) - 1.f;
}

// ---------------- pre-GEMM (unchanged from passing R5) ---------------------
template <int KDATA, int KP, bool FROMX>
__global__ void __launch_bounds__(512, 1) gemm_pre_mma(
    const float* __restrict__ src,   // FROMX: x [B][T][KDATA]; else g_ys1
    const float* __restrict__ w,     // [256][KDATA]
    const float* __restrict__ bia, const float* __restrict__ bib)
{
    constexpr int SA = KP + 8;
    extern __shared__ __nv_bfloat16 smh[];
    __nv_bfloat16* sWH = smh;
    __nv_bfloat16* sWL = sWH + 256 * SA;
    __nv_bfloat16* sAH = sWL + 256 * SA;
    __nv_bfloat16* sAL = sAH + 128 * SA;

    const int tid = threadIdx.x;
    for (int i = tid; i < 768 * SA / 2; i += 512)
        ((uint32_t*)smh)[i] = 0u;
    __syncthreads();

    for (int idx = tid; idx < 256 * KDATA; idx += 512) {
        int j = idx / KDATA, k = idx - j * KDATA;
        __nv_bfloat16 h, l;
        split_bf16(w[idx], h, l);
        sWH[j * SA + k] = h;
        sWL[j * SA + k] = l;
    }
    if (tid < 256) {
        __nv_bfloat16 h, l;
        split_bf16(bia[tid] + bib[tid], h, l);
        sWH[tid * SA + KDATA] = h;
        sWL[tid * SA + KDATA] = l;
    }
    if (tid < 128)
        sAH[tid * SA + KDATA] = __float2bfloat16(1.0f);

    const int lane = tid & 31, wid = tid >> 5;
    const int g = lane >> 2, tg = lane & 3;
    const int wRow = (wid & 3) * 32;
    const int wCol = (wid >> 2) * 64;

    for (int tile = blockIdx.x; tile < NTILES; tile += gridDim.x) {
        const int t = tile >> 4, b0 = (tile & 15) << 7;

        __syncthreads();
        for (int idx = tid; idx < 128 * (KDATA / 2); idx += 512) {
            int m = idx / (KDATA / 2), kp = idx - m * (KDATA / 2);
            const float* rp = FROMX
                ? src + ((size_t)(b0 + m) * T + t) * KDATA
                : g_ys1 + ((size_t)t * B + (b0 + m)) * KDATA;
            float2 v = *(const float2*)(rp + 2 * kp);
            __nv_bfloat16 h0, l0, h1, l1;
            split_bf16(v.x, h0, l0);
            split_bf16(v.y, h1, l1);
            sAH[m * SA + 2 * kp] = h0; sAH[m * SA + 2 * kp + 1] = h1;
            sAL[m * SA + 2 * kp] = l0; sAL[m * SA + 2 * kp + 1] = l1;
        }
        __syncthreads();

        float acc[2][8][4] = {};
        #pragma unroll
        for (int kk = 0; kk < KP / 16; ++kk) {
            uint32_t ah[2][4], al[2][4];
            #pragma unroll
            for (int f = 0; f < 2; ++f) {
                const int base = (wRow + f * 16 + g) * SA + kk * 16 + tg * 2;
                ah[f][0] = ld32bf(sAH + base);
                ah[f][1] = ld32bf(sAH + base + 8 * SA);
                ah[f][2] = ld32bf(sAH + base + 8);
                ah[f][3] = ld32bf(sAH + base + 8 * SA + 8);
                al[f][0] = ld32bf(sAL + base);
                al[f][1] = ld32bf(sAL + base + 8 * SA);
                al[f][2] = ld32bf(sAL + base + 8);
                al[f][3] = ld32bf(sAL + base + 8 * SA + 8);
            }
            #pragma unroll
            for (int n = 0; n < 8; ++n) {
                const int bbase = (wCol + n * 8 + g) * SA + kk * 16 + tg * 2;
                const uint32_t bh0 = ld32bf(sWH + bbase);
                const uint32_t bh1 = ld32bf(sWH + bbase + 8);
                const uint32_t bl0 = ld32bf(sWL + bbase);
                const uint32_t bl1 = ld32bf(sWL + bbase + 8);
                #pragma unroll
                for (int f = 0; f < 2; ++f) {
                    mma16816(acc[f][n], ah[f], bh0, bh1);
                    mma16816(acc[f][n], al[f], bh0, bh1);
                    mma16816(acc[f][n], ah[f], bl0, bl1);
                }
            }
        }

        float* orow = g_pre + ((size_t)t * B + b0) * G4;
        #pragma unroll
        for (int f = 0; f < 2; ++f) {
            const int r0 = wRow + f * 16 + g;
            #pragma unroll
            for (int n = 0; n < 8; ++n) {
                const int col = wCol + n * 8 + tg * 2;
                float2 v0 = make_float2(acc[f][n][0], acc[f][n][1]);
                float2 v1 = make_float2(acc[f][n][2], acc[f][n][3]);
                *(float2*)(orow + (size_t)r0 * G4 + col) = v0;
                *(float2*)(orow + (size_t)(r0 + 8) * G4 + col) = v1;
            }
        }
    }
}

// ---------------- recurrence via HMMA ------------------------------------
// CTA = 16 batch, 512 threads (16 warps). Warp w owns j in [16w, 16w+16).
// gates^T[j][b] = W_hh[j][k] * h[k][b]; A = W_hh (static regs, split),
// B = h (smem, bf16 pairs along k, split hi/lo).
template <bool ISL1>
__global__ void __launch_bounds__(512, 1) lstm_rec_mma(
    const float* __restrict__ w_hh,   // [256][64] row-major
    const float* __restrict__ fc_w,   // [O][H]  (L2 only)
    const float* __restrict__ fc_b,   // [O]     (L2 only)
    float* __restrict__ out)          // [B][O]  (L2 only)
{
    extern __shared__ uint32_t smu[];
    uint32_t* hBh = smu;                       // [32][HBS] h hi pairs
    uint32_t* hBl = smu + 32 * HBS;            // [32][HBS] h lo pairs
    float* sGate = (float*)(smu + 64 * HBS);   // [256][GS]
    float* sHL   = sGate + 256 * GS;           // [64][20] (L2 last h)

    const int tid = threadIdx.x;
    const int lane = tid & 31, w = tid >> 5;
    const int g = lane >> 2, tg = lane & 3;
    const int batch0 = blockIdx.x * 16;

    // zero h buffers (h0 = 0)
    for (int i = tid; i < 64 * HBS; i += 512) smu[i] = 0u;

    // static A fragments: W_hh split hi/lo, straight from gmem
    uint32_t a_h[4][4], a_l[4][4];
    #pragma unroll
    for (int kk = 0; kk < 4; ++kk) {
        #pragma unroll
        for (int r = 0; r < 4; ++r) {
            const int row = 16 * w + g + (r & 1) * 8;
            const int col = 16 * kk + 2 * tg + (r >> 1) * 8;
            float2 v = *(const float2*)(w_hh + row * 64 + col);
            __nv_bfloat16 h0, l0, h1, l1;
            split_bf16(v.x, h0, l0);
            split_bf16(v.y, h1, l1);
            a_h[kk][r] = packbf(h0, h1);
            a_l[kk][r] = packbf(l0, l1);
        }
    }

    // activation-phase roles: one h index, 2 batches
    const int hC = tid & 63;
    const int bC = (tid >> 6) * 2;
    float c_reg[2] = {0.f, 0.f};
    __syncthreads();

    for (int t = 0; t < T; ++t) {
        // prefetch additive pre-activations (consumed after BAR1)
        const float* pt = g_pre + ((size_t)t * B + batch0) * G4;
        float pv[2][4];
        #pragma unroll
        for (int q = 0; q < 2; ++q)
            #pragma unroll
            for (int p = 0; p < 4; ++p)
                pv[q][p] = pt[(bC + q) * G4 + p * 64 + hC];

        // MMA phase: B frags from hB, A static
        float acc[2][4] = {};
        #pragma unroll
        for (int nt = 0; nt < 2; ++nt) {
            #pragma unroll
            for (int kk = 0; kk < 4; ++kk) {
                const int c0 = (8 * kk + tg) * HBS + 8 * nt + g;
                const int c1 = (8 * kk + 4 + tg) * HBS + 8 * nt + g;
                const uint32_t bh0 = hBh[c0], bh1 = hBh[c1];
                const uint32_t bl0 = hBl[c0], bl1 = hBl[c1];
                mma16816(acc[nt], a_h[kk], bh0, bh1);   // Wh*hh
                mma16816(acc[nt], a_l[kk], bh0, bh1);   // Wl*hh
                mma16816(acc[nt], a_h[kk], bl0, bl1);   // Wh*hl
            }
        }
        // write gates^T to smem: thread owns rows j=16w+g, 16w+g+8
        #pragma unroll
        for (int nt = 0; nt < 2; ++nt) {
            *(float2*)(sGate + (16 * w + g) * GS + 8 * nt + 2 * tg) =
                make_float2(acc[nt][0], acc[nt][1]);
            *(float2*)(sGate + (16 * w + g + 8) * GS + 8 * nt + 2 * tg) =
                make_float2(acc[nt][2], acc[nt][3]);
        }
        __syncthreads();   // BAR1: gates visible; hB reads done

        // activation phase
        float2 G[4];
        #pragma unroll
        for (int p = 0; p < 4; ++p)
            G[p] = *(const float2*)(sGate + (hC + 64 * p) * GS + bC);
        #pragma unroll
        for (int q = 0; q < 2; ++q) {
            float gi = (q ? G[0].y : G[0].x) + pv[q][0];
            float gf = (q ? G[1].y : G[1].x) + pv[q][1];
            float gg = (q ? G[2].y : G[2].x) + pv[q][2];
            float go = (q ? G[3].y : G[3].x) + pv[q][3];
            gi = fsig(gi); gf = fsig(gf); go = fsig(go); gg = ftanh(gg);
            const float c = gf * c_reg[q] + gi * gg;
            c_reg[q] = c;
            const float hv = go * ftanh(c);
            // h split -> hB halfword stores (pair row = hC>>1, half = hC&1)
            __nv_bfloat16 hh, hl;
            split_bf16(hv, hh, hl);
            const int off = ((hC >> 1) * HBS + bC + q) * 2 + (hC & 1);
            ((unsigned short*)hBh)[off] = __bfloat16_as_ushort(hh);
            ((unsigned short*)hBl)[off] = __bfloat16_as_ushort(hl);
            if (ISL1)
                g_ys1[((size_t)t * B + batch0 + bC + q) * H + hC] = hv;
            else if (t == T - 1)
                sHL[hC * 20 + bC + q] = hv;
        }
        __syncthreads();   // BAR2: hB writes visible for next step
    }

    // L2: fused FC head out = h_last @ fc_w^T + fc_b
    if (!ISL1) {
        for (int idx = tid; idx < 16 * O; idx += 512) {
            int b = idx / O, o = idx - (idx / O) * O;
            float s = fc_b[o];
            #pragma unroll
            for (int h = 0; h < H; ++h)
                s += sHL[h * 20 + b] * fc_w[o * H + h];
            out[(batch0 + b) * O + o] = s;
        }
    }
}

extern "C" void kernel_launch(void* const* d_in, const int* in_sizes, int n_in,
                              void* d_out, int out_size) {
    const float* x     = (const float*)d_in[0];
    const float* w_ih0 = (const float*)d_in[1];
    const float* w_hh0 = (const float*)d_in[2];
    const float* b_ih0 = (const float*)d_in[3];
    const float* b_hh0 = (const float*)d_in[4];
    const float* w_ih1 = (const float*)d_in[5];
    const float* w_hh1 = (const float*)d_in[6];
    const float* b_ih1 = (const float*)d_in[7];
    const float* b_hh1 = (const float*)d_in[8];
    const float* fc_w  = (const float*)d_in[9];
    const float* fc_b  = (const float*)d_in[10];
    float* out = (float*)d_out;

    const int smG1 = 768 * (96 + 8) * 2;    // 159744 B
    const int smG2 = 768 * (80 + 8) * 2;    // 135168 B
    const int smR  = (64 * HBS + 256 * GS + 64 * 20) * 4 + 1024;  // ~35 KB

    cudaFuncSetAttribute(gemm_pre_mma<88, 96, true>,
                         cudaFuncAttributeMaxDynamicSharedMemorySize, smG1);
    cudaFuncSetAttribute(gemm_pre_mma<64, 80, false>,
                         cudaFuncAttributeMaxDynamicSharedMemorySize, smG2);
    cudaFuncSetAttribute(lstm_rec_mma<true>,
                         cudaFuncAttributeMaxDynamicSharedMemorySize, smR);
    cudaFuncSetAttribute(lstm_rec_mma<false>,
                         cudaFuncAttributeMaxDynamicSharedMemorySize, smR);

    gemm_pre_mma<88, 96, true><<<148, 512, smG1>>>(x, w_ih0, b_ih0, b_hh0);
    lstm_rec_mma<true><<<B / 16, 512, smR>>>(w_hh0, nullptr, nullptr, nullptr);
    gemm_pre_mma<64, 80, false><<<148, 512, smG2>>>(nullptr, w_ih1, b_ih1, b_hh1);
    lstm_rec_mma<false><<<B / 16, 512, smR>>>(w_hh1, fc_w, fc_b, out);
}

// round 8
// speedup vs baseline: 4.1090x; 1.0855x over previous
#include <cuda_runtime.h>
#include <cuda_bf16.h>
#include <cstdint>
#include <math.h>

// MusicRNN: 2-layer LSTM (B=2048, T=256, I=88, H=64) + FC (O=13).
// R7: gemm_pre2 FUSED into rec1. rec1 keeps TWO static A-fragment sets
// (W_hh0 and W_ih1, split hi/lo bf16) and per step reuses the same h
// B-fragments for both GEMMs: its own recurrent gates AND pre2[t-1] =
// W_ih1 @ h1[t-1] (written straight to g_pre2; bias added later in rec2).
// Deletes the standalone gemm2 kernel and all ys1 traffic.
// 3 kernels: gemm1 -> rec1(fused) -> rec2(+FC).

namespace {
constexpr int B = 2048, T = 256, I = 88, H = 64, O = 13, G4 = 256;
constexpr int NTILES = T * (B / 128);       // 4096 tiles of 128 rows
constexpr int HBS = 24;                      // hB row stride (words)
constexpr int GS  = 22;                      // sGate row stride (floats)
}

// scratch (static __device__: allocation-free rule)
__device__ float g_pre1[(size_t)T * B * G4];   // 512 MB: x @ W_ih0^T + bias0
__device__ float g_pre2[(size_t)T * B * G4];   // 512 MB: ys1 @ W_ih1^T (no bias)

typedef unsigned long long ull;

// ---------------- warp-MMA bf16 (baseline PTX, works on .target sm_103) ----
__device__ __forceinline__ void mma16816(float* c, const uint32_t* a,
                                         uint32_t b0, uint32_t b1) {
    asm volatile(
        "mma.sync.aligned.m16n8k16.row.col.f32.bf16.bf16.f32 "
        "{%0,%1,%2,%3}, {%4,%5,%6,%7}, {%8,%9}, {%0,%1,%2,%3};"
        : "+f"(c[0]), "+f"(c[1]), "+f"(c[2]), "+f"(c[3])
        : "r"(a[0]), "r"(a[1]), "r"(a[2]), "r"(a[3]), "r"(b0), "r"(b1));
}
__device__ __forceinline__ uint32_t ld32bf(const __nv_bfloat16* p) {
    return *(const uint32_t*)p;
}
__device__ __forceinline__ void split_bf16(float v, __nv_bfloat16& h,
                                           __nv_bfloat16& l) {
    h = __float2bfloat16(v);
    l = __float2bfloat16(v - __bfloat162float(h));
}
__device__ __forceinline__ uint32_t packbf(__nv_bfloat16 lo, __nv_bfloat16 hi) {
    return (uint32_t)__bfloat16_as_ushort(lo)
         | ((uint32_t)__bfloat16_as_ushort(hi) << 16);
}
__device__ __forceinline__ float fsig(float x) {
    return __fdividef(1.f, 1.f + __expf(-x));
}
__device__ __forceinline__ float ftanh(float x) {
    return __fdividef(2.f, 1.f + __expf(-2.f * x)) - 1.f;
}

// ---------------- pre-GEMM 1 (unchanged R5 design, writes g_pre1) ----------
template <int KDATA, int KP>
__global__ void __launch_bounds__(512, 1) gemm_pre_mma(
    const float* __restrict__ src,   // x [B][T][KDATA]
    const float* __restrict__ w,     // [256][KDATA]
    const float* __restrict__ bia, const float* __restrict__ bib)
{
    constexpr int SA = KP + 8;
    extern __shared__ __nv_bfloat16 smh[];
    __nv_bfloat16* sWH = smh;
    __nv_bfloat16* sWL = sWH + 256 * SA;
    __nv_bfloat16* sAH = sWL + 256 * SA;
    __nv_bfloat16* sAL = sAH + 128 * SA;

    const int tid = threadIdx.x;
    for (int i = tid; i < 768 * SA / 2; i += 512)
        ((uint32_t*)smh)[i] = 0u;
    __syncthreads();

    for (int idx = tid; idx < 256 * KDATA; idx += 512) {
        int j = idx / KDATA, k = idx - j * KDATA;
        __nv_bfloat16 h, l;
        split_bf16(w[idx], h, l);
        sWH[j * SA + k] = h;
        sWL[j * SA + k] = l;
    }
    if (tid < 256) {
        __nv_bfloat16 h, l;
        split_bf16(bia[tid] + bib[tid], h, l);
        sWH[tid * SA + KDATA] = h;
        sWL[tid * SA + KDATA] = l;
    }
    if (tid < 128)
        sAH[tid * SA + KDATA] = __float2bfloat16(1.0f);

    const int lane = tid & 31, wid = tid >> 5;
    const int g = lane >> 2, tg = lane & 3;
    const int wRow = (wid & 3) * 32;
    const int wCol = (wid >> 2) * 64;

    for (int tile = blockIdx.x; tile < NTILES; tile += gridDim.x) {
        const int t = tile >> 4, b0 = (tile & 15) << 7;

        __syncthreads();
        for (int idx = tid; idx < 128 * (KDATA / 2); idx += 512) {
            int m = idx / (KDATA / 2), kp = idx - m * (KDATA / 2);
            const float* rp = src + ((size_t)(b0 + m) * T + t) * KDATA;
            float2 v = *(const float2*)(rp + 2 * kp);
            __nv_bfloat16 h0, l0, h1, l1;
            split_bf16(v.x, h0, l0);
            split_bf16(v.y, h1, l1);
            sAH[m * SA + 2 * kp] = h0; sAH[m * SA + 2 * kp + 1] = h1;
            sAL[m * SA + 2 * kp] = l0; sAL[m * SA + 2 * kp + 1] = l1;
        }
        __syncthreads();

        float acc[2][8][4] = {};
        #pragma unroll
        for (int kk = 0; kk < KP / 16; ++kk) {
            uint32_t ah[2][4], al[2][4];
            #pragma unroll
            for (int f = 0; f < 2; ++f) {
                const int base = (wRow + f * 16 + g) * SA + kk * 16 + tg * 2;
                ah[f][0] = ld32bf(sAH + base);
                ah[f][1] = ld32bf(sAH + base + 8 * SA);
                ah[f][2] = ld32bf(sAH + base + 8);
                ah[f][3] = ld32bf(sAH + base + 8 * SA + 8);
                al[f][0] = ld32bf(sAL + base);
                al[f][1] = ld32bf(sAL + base + 8 * SA);
                al[f][2] = ld32bf(sAL + base + 8);
                al[f][3] = ld32bf(sAL + base + 8 * SA + 8);
            }
            #pragma unroll
            for (int n = 0; n < 8; ++n) {
                const int bbase = (wCol + n * 8 + g) * SA + kk * 16 + tg * 2;
                const uint32_t bh0 = ld32bf(sWH + bbase);
                const uint32_t bh1 = ld32bf(sWH + bbase + 8);
                const uint32_t bl0 = ld32bf(sWL + bbase);
                const uint32_t bl1 = ld32bf(sWL + bbase + 8);
                #pragma unroll
                for (int f = 0; f < 2; ++f) {
                    mma16816(acc[f][n], ah[f], bh0, bh1);
                    mma16816(acc[f][n], al[f], bh0, bh1);
                    mma16816(acc[f][n], ah[f], bl0, bl1);
                }
            }
        }

        float* orow = g_pre1 + ((size_t)t * B + b0) * G4;
        #pragma unroll
        for (int f = 0; f < 2; ++f) {
            const int r0 = wRow + f * 16 + g;
            #pragma unroll
            for (int n = 0; n < 8; ++n) {
                const int col = wCol + n * 8 + tg * 2;
                float2 v0 = make_float2(acc[f][n][0], acc[f][n][1]);
                float2 v1 = make_float2(acc[f][n][2], acc[f][n][3]);
                *(float2*)(orow + (size_t)r0 * G4 + col) = v0;
                *(float2*)(orow + (size_t)(r0 + 8) * G4 + col) = v1;
            }
        }
    }
}

// ---------------- recurrence via HMMA, L1 fused with pre2 production -------
// CTA = 16 batch, 512 threads (16 warps). Warp w owns j in [16w, 16w+16).
// ISL1: also computes pre2[t-1] = W_ih1 @ h1[t-1] each step (same B-frags).
template <bool ISL1>
__global__ void __launch_bounds__(512, 1) lstm_rec_mma(
    const float* __restrict__ w_hh,   // [256][64]
    const float* __restrict__ w_ih1,  // [256][64] (L1 only: layer-2 W_ih)
    const float* __restrict__ bi1,    // [256] (L2 only: b_ih1)
    const float* __restrict__ bh1,    // [256] (L2 only: b_hh1)
    const float* __restrict__ fc_w,   // [O][H]  (L2 only)
    const float* __restrict__ fc_b,   // [O]     (L2 only)
    float* __restrict__ out)          // [B][O]  (L2 only)
{
    extern __shared__ uint32_t smu[];
    uint32_t* hBh = smu;                       // [32][HBS] h hi pairs
    uint32_t* hBl = smu + 32 * HBS;            // [32][HBS] h lo pairs
    float* sGate = (float*)(smu + 64 * HBS);   // [256][GS]
    float* sHL   = sGate + 256 * GS;           // [64][20] (L2 last h)

    const int tid = threadIdx.x;
    const int lane = tid & 31, w = tid >> 5;
    const int g = lane >> 2, tg = lane & 3;
    const int batch0 = blockIdx.x * 16;

    for (int i = tid; i < 64 * HBS; i += 512) smu[i] = 0u;  // h0 = 0

    // static A fragments: W_hh split hi/lo
    uint32_t a_h[4][4], a_l[4][4];
    // L1 only: second set for W_ih1
    uint32_t c_h[4][4], c_l[4][4];
    #pragma unroll
    for (int kk = 0; kk < 4; ++kk) {
        #pragma unroll
        for (int r = 0; r < 4; ++r) {
            const int row = 16 * w + g + (r & 1) * 8;
            const int col = 16 * kk + 2 * tg + (r >> 1) * 8;
            float2 v = *(const float2*)(w_hh + row * 64 + col);
            __nv_bfloat16 h0, l0, h1, l1;
            split_bf16(v.x, h0, l0);
            split_bf16(v.y, h1, l1);
            a_h[kk][r] = packbf(h0, h1);
            a_l[kk][r] = packbf(l0, l1);
            if (ISL1) {
                float2 u = *(const float2*)(w_ih1 + row * 64 + col);
                split_bf16(u.x, h0, l0);
                split_bf16(u.y, h1, l1);
                c_h[kk][r] = packbf(h0, h1);
                c_l[kk][r] = packbf(l0, l1);
            }
        }
    }

    // activation-phase roles
    const int hC = tid & 63;
    const int bC = (tid >> 6) * 2;
    float c_reg[2] = {0.f, 0.f};
    // L2: per-thread bias (b_ih1 + b_hh1) for the 4 gate slots
    float bv[4] = {0.f, 0.f, 0.f, 0.f};
    if (!ISL1) {
        #pragma unroll
        for (int p = 0; p < 4; ++p)
            bv[p] = bi1[p * 64 + hC] + bh1[p * 64 + hC];
    }
    __syncthreads();

    for (int t = 0; t < T; ++t) {
        // prefetch additive pre-activations (pre1 or pre2)
        const float* pt = (ISL1 ? g_pre1 : g_pre2) + ((size_t)t * B + batch0) * G4;
        float pv[2][4];
        #pragma unroll
        for (int q = 0; q < 2; ++q)
            #pragma unroll
            for (int p = 0; p < 4; ++p)
                pv[q][p] = pt[(bC + q) * G4 + p * 64 + hC];

        // MMA phase: shared B frags feed both GEMMs; 4 interleaved chains
        float acc[2][4] = {};
        float acc2[2][4] = {};
        #pragma unroll
        for (int kk = 0; kk < 4; ++kk) {
            #pragma unroll
            for (int nt = 0; nt < 2; ++nt) {
                const int c0 = (8 * kk + tg) * HBS + 8 * nt + g;
                const int c1 = (8 * kk + 4 + tg) * HBS + 8 * nt + g;
                const uint32_t bh0 = hBh[c0], bh1v = hBh[c1];
                const uint32_t bl0 = hBl[c0], bl1v = hBl[c1];
                mma16816(acc[nt], a_h[kk], bh0, bh1v);
                if (ISL1) mma16816(acc2[nt], c_h[kk], bh0, bh1v);
                mma16816(acc[nt], a_l[kk], bh0, bh1v);
                if (ISL1) mma16816(acc2[nt], c_l[kk], bh0, bh1v);
                mma16816(acc[nt], a_h[kk], bl0, bl1v);
                if (ISL1) mma16816(acc2[nt], c_h[kk], bl0, bl1v);
            }
        }
        // gates^T -> smem
        #pragma unroll
        for (int nt = 0; nt < 2; ++nt) {
            *(float2*)(sGate + (16 * w + g) * GS + 8 * nt + 2 * tg) =
                make_float2(acc[nt][0], acc[nt][1]);
            *(float2*)(sGate + (16 * w + g + 8) * GS + 8 * nt + 2 * tg) =
                make_float2(acc[nt][2], acc[nt][3]);
        }
        // pre2[t-1] -> gmem (acc2 used h[t-1]); overlaps BAR1 wait
        if (ISL1 && t > 0) {
            float* dst = g_pre2 + ((size_t)(t - 1) * B + batch0) * G4;
            #pragma unroll
            for (int nt = 0; nt < 2; ++nt) {
                const int b = 8 * nt + 2 * tg;
                dst[(size_t)b * G4 + 16 * w + g]           = acc2[nt][0];
                dst[(size_t)(b + 1) * G4 + 16 * w + g]     = acc2[nt][1];
                dst[(size_t)b * G4 + 16 * w + g + 8]       = acc2[nt][2];
                dst[(size_t)(b + 1) * G4 + 16 * w + g + 8] = acc2[nt][3];
            }
        }
        __syncthreads();   // BAR1: gates visible; hB reads done

        // activation phase
        float2 G[4];
        #pragma unroll
        for (int p = 0; p < 4; ++p)
            G[p] = *(const float2*)(sGate + (hC + 64 * p) * GS + bC);
        #pragma unroll
        for (int q = 0; q < 2; ++q) {
            float gi = (q ? G[0].y : G[0].x) + pv[q][0] + bv[0];
            float gf = (q ? G[1].y : G[1].x) + pv[q][1] + bv[1];
            float gg = (q ? G[2].y : G[2].x) + pv[q][2] + bv[2];
            float go = (q ? G[3].y : G[3].x) + pv[q][3] + bv[3];
            gi = fsig(gi); gf = fsig(gf); go = fsig(go); gg = ftanh(gg);
            const float c = gf * c_reg[q] + gi * gg;
            c_reg[q] = c;
            const float hv = go * ftanh(c);
            __nv_bfloat16 hh, hl;
            split_bf16(hv, hh, hl);
            const int off = ((hC >> 1) * HBS + bC + q) * 2 + (hC & 1);
            ((unsigned short*)hBh)[off] = __bfloat16_as_ushort(hh);
            ((unsigned short*)hBl)[off] = __bfloat16_as_ushort(hl);
            if (!ISL1 && t == T - 1)
                sHL[hC * 20 + bC + q] = hv;
        }
        __syncthreads();   // BAR2: hB writes visible for next step
    }

    if (ISL1) {
        // final pre2[T-1] from h[T-1]
        float acc2[2][4] = {};
        #pragma unroll
        for (int kk = 0; kk < 4; ++kk) {
            #pragma unroll
            for (int nt = 0; nt < 2; ++nt) {
                const int c0 = (8 * kk + tg) * HBS + 8 * nt + g;
                const int c1 = (8 * kk + 4 + tg) * HBS + 8 * nt + g;
                const uint32_t bh0 = hBh[c0], bh1v = hBh[c1];
                const uint32_t bl0 = hBl[c0], bl1v = hBl[c1];
                mma16816(acc2[nt], c_h[kk], bh0, bh1v);
                mma16816(acc2[nt], c_l[kk], bh0, bh1v);
                mma16816(acc2[nt], c_h[kk], bl0, bl1v);
            }
        }
        float* dst = g_pre2 + ((size_t)(T - 1) * B + batch0) * G4;
        #pragma unroll
        for (int nt = 0; nt < 2; ++nt) {
            const int b = 8 * nt + 2 * tg;
            dst[(size_t)b * G4 + 16 * w + g]           = acc2[nt][0];
            dst[(size_t)(b + 1) * G4 + 16 * w + g]     = acc2[nt][1];
            dst[(size_t)b * G4 + 16 * w + g + 8]       = acc2[nt][2];
            dst[(size_t)(b + 1) * G4 + 16 * w + g + 8] = acc2[nt][3];
        }
    } else {
        // fused FC head: out = h_last @ fc_w^T + fc_b
        for (int idx = tid; idx < 16 * O; idx += 512) {
            int b = idx / O, o = idx - (idx / O) * O;
            float s = fc_b[o];
            #pragma unroll
            for (int h = 0; h < H; ++h)
                s += sHL[h * 20 + b] * fc_w[o * H + h];
            out[(batch0 + b) * O + o] = s;
        }
    }
}

extern "C" void kernel_launch(void* const* d_in, const int* in_sizes, int n_in,
                              void* d_out, int out_size) {
    const float* x     = (const float*)d_in[0];
    const float* w_ih0 = (const float*)d_in[1];
    const float* w_hh0 = (const float*)d_in[2];
    const float* b_ih0 = (const float*)d_in[3];
    const float* b_hh0 = (const float*)d_in[4];
    const float* w_ih1 = (const float*)d_in[5];
    const float* w_hh1 = (const float*)d_in[6];
    const float* b_ih1 = (const float*)d_in[7];
    const float* b_hh1 = (const float*)d_in[8];
    const float* fc_w  = (const float*)d_in[9];
    const float* fc_b  = (const float*)d_in[10];
    float* out = (float*)d_out;

    const int smG1 = 768 * (96 + 8) * 2;    // 159744 B
    const int smR  = (64 * HBS + 256 * GS + 64 * 20) * 4 + 1024;  // ~35 KB

    cudaFuncSetAttribute(gemm_pre_mma<88, 96>,
                         cudaFuncAttributeMaxDynamicSharedMemorySize, smG1);
    cudaFuncSetAttribute(lstm_rec_mma<true>,
                         cudaFuncAttributeMaxDynamicSharedMemorySize, smR);
    cudaFuncSetAttribute(lstm_rec_mma<false>,
                         cudaFuncAttributeMaxDynamicSharedMemorySize, smR);

    gemm_pre_mma<88, 96><<<148, 512, smG1>>>(x, w_ih0, b_ih0, b_hh0);
    lstm_rec_mma<true><<<B / 16, 512, smR>>>(
        w_hh0, w_ih1, nullptr, nullptr, nullptr, nullptr, nullptr);
    lstm_rec_mma<false><<<B / 16, 512, smR>>>(
        w_hh1, nullptr, b_ih1, b_hh1, fc_w, fc_b, out);
}

// round 9
// speedup vs baseline: 4.1155x; 1.0016x over previous
#include <cuda_runtime.h>
#include <cuda_bf16.h>
#include <cstdint>
#include <math.h>

// MusicRNN: 2-layer LSTM (B=2048, T=256, I=88, H=64) + FC (O=13).
// R8: software-pipeline the g_pre reads in both recurrence kernels by ONE
// FULL STEP (double-buffered registers) so the ~600-1000cyc gmem latency is
// hidden behind the previous step's MMA+activation. All g_pre traffic uses
// streaming hints (__ldcs/__stcs) to keep the 512MB streams out of L2's way.
// Structure unchanged from R7: gemm1 -> rec1(fused pre2 production) -> rec2.

namespace {
constexpr int B = 2048, T = 256, I = 88, H = 64, O = 13, G4 = 256;
constexpr int NTILES = T * (B / 128);       // 4096 tiles of 128 rows
constexpr int HBS = 24;                      // hB row stride (words)
constexpr int GS  = 22;                      // sGate row stride (floats)
}

// scratch (static __device__: allocation-free rule)
__device__ float g_pre1[(size_t)T * B * G4];   // 512 MB: x @ W_ih0^T + bias0
__device__ float g_pre2[(size_t)T * B * G4];   // 512 MB: ys1 @ W_ih1^T (no bias)

typedef unsigned long long ull;

// ---------------- warp-MMA bf16 (baseline PTX, works on .target sm_103) ----
__device__ __forceinline__ void mma16816(float* c, const uint32_t* a,
                                         uint32_t b0, uint32_t b1) {
    asm volatile(
        "mma.sync.aligned.m16n8k16.row.col.f32.bf16.bf16.f32 "
        "{%0,%1,%2,%3}, {%4,%5,%6,%7}, {%8,%9}, {%0,%1,%2,%3};"
        : "+f"(c[0]), "+f"(c[1]), "+f"(c[2]), "+f"(c[3])
        : "r"(a[0]), "r"(a[1]), "r"(a[2]), "r"(a[3]), "r"(b0), "r"(b1));
}
__device__ __forceinline__ uint32_t ld32bf(const __nv_bfloat16* p) {
    return *(const uint32_t*)p;
}
__device__ __forceinline__ void split_bf16(float v, __nv_bfloat16& h,
                                           __nv_bfloat16& l) {
    h = __float2bfloat16(v);
    l = __float2bfloat16(v - __bfloat162float(h));
}
__device__ __forceinline__ uint32_t packbf(__nv_bfloat16 lo, __nv_bfloat16 hi) {
    return (uint32_t)__bfloat16_as_ushort(lo)
         | ((uint32_t)__bfloat16_as_ushort(hi) << 16);
}
__device__ __forceinline__ float fsig(float x) {
    return __fdividef(1.f, 1.f + __expf(-x));
}
__device__ __forceinline__ float ftanh(float x) {
    return __fdividef(2.f, 1.f + __expf(-2.f * x)) - 1.f;
}

// ---------------- pre-GEMM 1 (R5 design + streaming stores) ----------------
template <int KDATA, int KP>
__global__ void __launch_bounds__(512, 1) gemm_pre_mma(
    const float* __restrict__ src,   // x [B][T][KDATA]
    const float* __restrict__ w,     // [256][KDATA]
    const float* __restrict__ bia, const float* __restrict__ bib)
{
    constexpr int SA = KP + 8;
    extern __shared__ __nv_bfloat16 smh[];
    __nv_bfloat16* sWH = smh;
    __nv_bfloat16* sWL = sWH + 256 * SA;
    __nv_bfloat16* sAH = sWL + 256 * SA;
    __nv_bfloat16* sAL = sAH + 128 * SA;

    const int tid = threadIdx.x;
    for (int i = tid; i < 768 * SA / 2; i += 512)
        ((uint32_t*)smh)[i] = 0u;
    __syncthreads();

    for (int idx = tid; idx < 256 * KDATA; idx += 512) {
        int j = idx / KDATA, k = idx - j * KDATA;
        __nv_bfloat16 h, l;
        split_bf16(w[idx], h, l);
        sWH[j * SA + k] = h;
        sWL[j * SA + k] = l;
    }
    if (tid < 256) {
        __nv_bfloat16 h, l;
        split_bf16(bia[tid] + bib[tid], h, l);
        sWH[tid * SA + KDATA] = h;
        sWL[tid * SA + KDATA] = l;
    }
    if (tid < 128)
        sAH[tid * SA + KDATA] = __float2bfloat16(1.0f);

    const int lane = tid & 31, wid = tid >> 5;
    const int g = lane >> 2, tg = lane & 3;
    const int wRow = (wid & 3) * 32;
    const int wCol = (wid >> 2) * 64;

    for (int tile = blockIdx.x; tile < NTILES; tile += gridDim.x) {
        const int t = tile >> 4, b0 = (tile & 15) << 7;

        __syncthreads();
        for (int idx = tid; idx < 128 * (KDATA / 2); idx += 512) {
            int m = idx / (KDATA / 2), kp = idx - m * (KDATA / 2);
            const float* rp = src + ((size_t)(b0 + m) * T + t) * KDATA;
            float2 v = *(const float2*)(rp + 2 * kp);
            __nv_bfloat16 h0, l0, h1, l1;
            split_bf16(v.x, h0, l0);
            split_bf16(v.y, h1, l1);
            sAH[m * SA + 2 * kp] = h0; sAH[m * SA + 2 * kp + 1] = h1;
            sAL[m * SA + 2 * kp] = l0; sAL[m * SA + 2 * kp + 1] = l1;
        }
        __syncthreads();

        float acc[2][8][4] = {};
        #pragma unroll
        for (int kk = 0; kk < KP / 16; ++kk) {
            uint32_t ah[2][4], al[2][4];
            #pragma unroll
            for (int f = 0; f < 2; ++f) {
                const int base = (wRow + f * 16 + g) * SA + kk * 16 + tg * 2;
                ah[f][0] = ld32bf(sAH + base);
                ah[f][1] = ld32bf(sAH + base + 8 * SA);
                ah[f][2] = ld32bf(sAH + base + 8);
                ah[f][3] = ld32bf(sAH + base + 8 * SA + 8);
                al[f][0] = ld32bf(sAL + base);
                al[f][1] = ld32bf(sAL + base + 8 * SA);
                al[f][2] = ld32bf(sAL + base + 8);
                al[f][3] = ld32bf(sAL + base + 8 * SA + 8);
            }
            #pragma unroll
            for (int n = 0; n < 8; ++n) {
                const int bbase = (wCol + n * 8 + g) * SA + kk * 16 + tg * 2;
                const uint32_t bh0 = ld32bf(sWH + bbase);
                const uint32_t bh1 = ld32bf(sWH + bbase + 8);
                const uint32_t bl0 = ld32bf(sWL + bbase);
                const uint32_t bl1 = ld32bf(sWL + bbase + 8);
                #pragma unroll
                for (int f = 0; f < 2; ++f) {
                    mma16816(acc[f][n], ah[f], bh0, bh1);
                    mma16816(acc[f][n], al[f], bh0, bh1);
                    mma16816(acc[f][n], ah[f], bl0, bl1);
                }
            }
        }

        float* orow = g_pre1 + ((size_t)t * B + b0) * G4;
        #pragma unroll
        for (int f = 0; f < 2; ++f) {
            const int r0 = wRow + f * 16 + g;
            #pragma unroll
            for (int n = 0; n < 8; ++n) {
                const int col = wCol + n * 8 + tg * 2;
                __stcs((float2*)(orow + (size_t)r0 * G4 + col),
                       make_float2(acc[f][n][0], acc[f][n][1]));
                __stcs((float2*)(orow + (size_t)(r0 + 8) * G4 + col),
                       make_float2(acc[f][n][2], acc[f][n][3]));
            }
        }
    }
}

// ---------------- recurrence via HMMA, L1 fused with pre2 production -------
// CTA = 16 batch, 512 threads (16 warps). Warp w owns j in [16w, 16w+16).
// g_pre reads are software-pipelined ONE STEP AHEAD (pvA/pvB reg buffers).
template <bool ISL1>
__global__ void __launch_bounds__(512, 1) lstm_rec_mma(
    const float* __restrict__ w_hh,   // [256][64]
    const float* __restrict__ w_ih1,  // [256][64] (L1 only)
    const float* __restrict__ bi1,    // [256] (L2 only)
    const float* __restrict__ bh1,    // [256] (L2 only)
    const float* __restrict__ fc_w,   // [O][H]  (L2 only)
    const float* __restrict__ fc_b,   // [O]     (L2 only)
    float* __restrict__ out)          // [B][O]  (L2 only)
{
    extern __shared__ uint32_t smu[];
    uint32_t* hBh = smu;                       // [32][HBS] h hi pairs
    uint32_t* hBl = smu + 32 * HBS;            // [32][HBS] h lo pairs
    float* sGate = (float*)(smu + 64 * HBS);   // [256][GS]
    float* sHL   = sGate + 256 * GS;           // [64][20] (L2 last h)

    const int tid = threadIdx.x;
    const int lane = tid & 31, w = tid >> 5;
    const int g = lane >> 2, tg = lane & 3;
    const int batch0 = blockIdx.x * 16;

    for (int i = tid; i < 64 * HBS; i += 512) smu[i] = 0u;  // h0 = 0

    uint32_t a_h[4][4], a_l[4][4];
    uint32_t c_h[4][4], c_l[4][4];
    #pragma unroll
    for (int kk = 0; kk < 4; ++kk) {
        #pragma unroll
        for (int r = 0; r < 4; ++r) {
            const int row = 16 * w + g + (r & 1) * 8;
            const int col = 16 * kk + 2 * tg + (r >> 1) * 8;
            float2 v = *(const float2*)(w_hh + row * 64 + col);
            __nv_bfloat16 h0, l0, h1, l1;
            split_bf16(v.x, h0, l0);
            split_bf16(v.y, h1, l1);
            a_h[kk][r] = packbf(h0, h1);
            a_l[kk][r] = packbf(l0, l1);
            if (ISL1) {
                float2 u = *(const float2*)(w_ih1 + row * 64 + col);
                split_bf16(u.x, h0, l0);
                split_bf16(u.y, h1, l1);
                c_h[kk][r] = packbf(h0, h1);
                c_l[kk][r] = packbf(l0, l1);
            }
        }
    }

    const int hC = tid & 63;
    const int bC = (tid >> 6) * 2;
    float c_reg[2] = {0.f, 0.f};
    float bv[4] = {0.f, 0.f, 0.f, 0.f};
    if (!ISL1) {
        #pragma unroll
        for (int p = 0; p < 4; ++p)
            bv[p] = bi1[p * 64 + hC] + bh1[p * 64 + hC];
    }

    const float* preSrc = ISL1 ? g_pre1 : g_pre2;
    // pipelined pre buffers: pvA holds step t data when t even, pvB when odd
    float pvA[2][4], pvB[2][4];
    {
        const float* pt = preSrc + (size_t)batch0 * G4;
        #pragma unroll
        for (int q = 0; q < 2; ++q)
            #pragma unroll
            for (int p = 0; p < 4; ++p)
                pvA[q][p] = __ldcs(&pt[(bC + q) * G4 + p * 64 + hC]);
    }
    __syncthreads();

    #pragma unroll 2
    for (int t = 0; t < T; ++t) {
        float (&pv)[2][4] = (t & 1) ? pvB : pvA;
        float (&nv)[2][4] = (t & 1) ? pvA : pvB;

        // prefetch NEXT step's pre (consumed next iteration -> full overlap)
        if (t + 1 < T) {
            const float* pt = preSrc + ((size_t)(t + 1) * B + batch0) * G4;
            #pragma unroll
            for (int q = 0; q < 2; ++q)
                #pragma unroll
                for (int p = 0; p < 4; ++p)
                    nv[q][p] = __ldcs(&pt[(bC + q) * G4 + p * 64 + hC]);
        }

        // MMA phase: shared B frags feed both GEMMs
        float acc[2][4] = {};
        float acc2[2][4] = {};
        #pragma unroll
        for (int kk = 0; kk < 4; ++kk) {
            #pragma unroll
            for (int nt = 0; nt < 2; ++nt) {
                const int c0 = (8 * kk + tg) * HBS + 8 * nt + g;
                const int c1 = (8 * kk + 4 + tg) * HBS + 8 * nt + g;
                const uint32_t bh0 = hBh[c0], bh1v = hBh[c1];
                const uint32_t bl0 = hBl[c0], bl1v = hBl[c1];
                mma16816(acc[nt], a_h[kk], bh0, bh1v);
                if (ISL1) mma16816(acc2[nt], c_h[kk], bh0, bh1v);
                mma16816(acc[nt], a_l[kk], bh0, bh1v);
                if (ISL1) mma16816(acc2[nt], c_l[kk], bh0, bh1v);
                mma16816(acc[nt], a_h[kk], bl0, bl1v);
                if (ISL1) mma16816(acc2[nt], c_h[kk], bl0, bl1v);
            }
        }
        #pragma unroll
        for (int nt = 0; nt < 2; ++nt) {
            *(float2*)(sGate + (16 * w + g) * GS + 8 * nt + 2 * tg) =
                make_float2(acc[nt][0], acc[nt][1]);
            *(float2*)(sGate + (16 * w + g + 8) * GS + 8 * nt + 2 * tg) =
                make_float2(acc[nt][2], acc[nt][3]);
        }
        // pre2[t-1] -> gmem (streaming); overlaps BAR1 wait
        if (ISL1 && t > 0) {
            float* dst = g_pre2 + ((size_t)(t - 1) * B + batch0) * G4;
            #pragma unroll
            for (int nt = 0; nt < 2; ++nt) {
                const int b = 8 * nt + 2 * tg;
                __stcs(&dst[(size_t)b * G4 + 16 * w + g], acc2[nt][0]);
                __stcs(&dst[(size_t)(b + 1) * G4 + 16 * w + g], acc2[nt][1]);
                __stcs(&dst[(size_t)b * G4 + 16 * w + g + 8], acc2[nt][2]);
                __stcs(&dst[(size_t)(b + 1) * G4 + 16 * w + g + 8], acc2[nt][3]);
            }
        }
        __syncthreads();   // BAR1: gates visible; hB reads done

        // activation phase (uses pv, loaded LAST iteration)
        float2 G[4];
        #pragma unroll
        for (int p = 0; p < 4; ++p)
            G[p] = *(const float2*)(sGate + (hC + 64 * p) * GS + bC);
        #pragma unroll
        for (int q = 0; q < 2; ++q) {
            float gi = (q ? G[0].y : G[0].x) + pv[q][0] + bv[0];
            float gf = (q ? G[1].y : G[1].x) + pv[q][1] + bv[1];
            float gg = (q ? G[2].y : G[2].x) + pv[q][2] + bv[2];
            float go = (q ? G[3].y : G[3].x) + pv[q][3] + bv[3];
            gi = fsig(gi); gf = fsig(gf); go = fsig(go); gg = ftanh(gg);
            const float c = gf * c_reg[q] + gi * gg;
            c_reg[q] = c;
            const float hv = go * ftanh(c);
            __nv_bfloat16 hh, hl;
            split_bf16(hv, hh, hl);
            const int off = ((hC >> 1) * HBS + bC + q) * 2 + (hC & 1);
            ((unsigned short*)hBh)[off] = __bfloat16_as_ushort(hh);
            ((unsigned short*)hBl)[off] = __bfloat16_as_ushort(hl);
            if (!ISL1 && t == T - 1)
                sHL[hC * 20 + bC + q] = hv;
        }
        __syncthreads();   // BAR2: hB writes visible for next step
    }

    if (ISL1) {
        // final pre2[T-1] from h[T-1]
        float acc2[2][4] = {};
        #pragma unroll
        for (int kk = 0; kk < 4; ++kk) {
            #pragma unroll
            for (int nt = 0; nt < 2; ++nt) {
                const int c0 = (8 * kk + tg) * HBS + 8 * nt + g;
                const int c1 = (8 * kk + 4 + tg) * HBS + 8 * nt + g;
                const uint32_t bh0 = hBh[c0], bh1v = hBh[c1];
                const uint32_t bl0 = hBl[c0], bl1v = hBl[c1];
                mma16816(acc2[nt], c_h[kk], bh0, bh1v);
                mma16816(acc2[nt], c_l[kk], bh0, bh1v);
                mma16816(acc2[nt], c_h[kk], bl0, bl1v);
            }
        }
        float* dst = g_pre2 + ((size_t)(T - 1) * B + batch0) * G4;
        #pragma unroll
        for (int nt = 0; nt < 2; ++nt) {
            const int b = 8 * nt + 2 * tg;
            __stcs(&dst[(size_t)b * G4 + 16 * w + g], acc2[nt][0]);
            __stcs(&dst[(size_t)(b + 1) * G4 + 16 * w + g], acc2[nt][1]);
            __stcs(&dst[(size_t)b * G4 + 16 * w + g + 8], acc2[nt][2]);
            __stcs(&dst[(size_t)(b + 1) * G4 + 16 * w + g + 8], acc2[nt][3]);
        }
    } else {
        for (int idx = tid; idx < 16 * O; idx += 512) {
            int b = idx / O, o = idx - (idx / O) * O;
            float s = fc_b[o];
            #pragma unroll
            for (int h = 0; h < H; ++h)
                s += sHL[h * 20 + b] * fc_w[o * H + h];
            out[(batch0 + b) * O + o] = s;
        }
    }
}

extern "C" void kernel_launch(void* const* d_in, const int* in_sizes, int n_in,
                              void* d_out, int out_size) {
    const float* x     = (const float*)d_in[0];
    const float* w_ih0 = (const float*)d_in[1];
    const float* w_hh0 = (const float*)d_in[2];
    const float* b_ih0 = (const float*)d_in[3];
    const float* b_hh0 = (const float*)d_in[4];
    const float* w_ih1 = (const float*)d_in[5];
    const float* w_hh1 = (const float*)d_in[6];
    const float* b_ih1 = (const float*)d_in[7];
    const float* b_hh1 = (const float*)d_in[8];
    const float* fc_w  = (const float*)d_in[9];
    const float* fc_b  = (const float*)d_in[10];
    float* out = (float*)d_out;

    const int smG1 = 768 * (96 + 8) * 2;    // 159744 B
    const int smR  = (64 * HBS + 256 * GS + 64 * 20) * 4 + 1024;  // ~35 KB

    cudaFuncSetAttribute(gemm_pre_mma<88, 96>,
                         cudaFuncAttributeMaxDynamicSharedMemorySize, smG1);
    cudaFuncSetAttribute(lstm_rec_mma<true>,
                         cudaFuncAttributeMaxDynamicSharedMemorySize, smR);
    cudaFuncSetAttribute(lstm_rec_mma<false>,
                         cudaFuncAttributeMaxDynamicSharedMemorySize, smR);

    gemm_pre_mma<88, 96><<<148, 512, smG1>>>(x, w_ih0, b_ih0, b_hh0);
    lstm_rec_mma<true><<<B / 16, 512, smR>>>(
        w_hh0, w_ih1, nullptr, nullptr, nullptr, nullptr, nullptr);
    lstm_rec_mma<false><<<B / 16, 512, smR>>>(
        w_hh1, nullptr, b_ih1, b_hh1, fc_w, fc_b, out);
}

// round 10
// speedup vs baseline: 4.4976x; 1.0929x over previous
#include <cuda_runtime.h>
#include <cuda_bf16.h>
#include <cstdint>
#include <math.h>

// MusicRNN: 2-layer LSTM (B=2048, T=256, I=88, H=64) + FC (O=13).
// R9: BOTH LSTM layers fused into ONE recurrence kernel with 1-step skew:
// at step t the MMA phase computes gates1[t] (W_hh0@h1[t-1]) and
// gates2[t-1] (W_ih1@h1[t-1] + W_hh1@h2[t-2], single accumulator); the
// activation phase updates h1[t] AND h2[t-1]. Deletes the rec2 launch and
// all g_pre2 gmem traffic. W_hh1 fragments cached in per-thread SMEM.
// 2 kernels: gemm1 -> fused rec (+FC head).

namespace {
constexpr int B = 2048, T = 256, I = 88, H = 64, O = 13, G4 = 256;
constexpr int NTILES = T * (B / 128);       // 4096 tiles of 128 rows
constexpr int HBS = 24;                      // hB row stride (words)
constexpr int GS  = 22;                      // sGate row stride (floats)
}

// scratch (static __device__: allocation-free rule)
__device__ float g_pre1[(size_t)T * B * G4];   // 512 MB: x @ W_ih0^T + bias0

typedef unsigned long long ull;

// ---------------- warp-MMA bf16 (baseline PTX, works on .target sm_103) ----
__device__ __forceinline__ void mma16816(float* c, const uint32_t* a,
                                         uint32_t b0, uint32_t b1) {
    asm volatile(
        "mma.sync.aligned.m16n8k16.row.col.f32.bf16.bf16.f32 "
        "{%0,%1,%2,%3}, {%4,%5,%6,%7}, {%8,%9}, {%0,%1,%2,%3};"
        : "+f"(c[0]), "+f"(c[1]), "+f"(c[2]), "+f"(c[3])
        : "r"(a[0]), "r"(a[1]), "r"(a[2]), "r"(a[3]), "r"(b0), "r"(b1));
}
__device__ __forceinline__ uint32_t ld32bf(const __nv_bfloat16* p) {
    return *(const uint32_t*)p;
}
__device__ __forceinline__ void split_bf16(float v, __nv_bfloat16& h,
                                           __nv_bfloat16& l) {
    h = __float2bfloat16(v);
    l = __float2bfloat16(v - __bfloat162float(h));
}
__device__ __forceinline__ uint32_t packbf(__nv_bfloat16 lo, __nv_bfloat16 hi) {
    return (uint32_t)__bfloat16_as_ushort(lo)
         | ((uint32_t)__bfloat16_as_ushort(hi) << 16);
}
__device__ __forceinline__ float fsig(float x) {
    return __fdividef(1.f, 1.f + __expf(-x));
}
__device__ __forceinline__ float ftanh(float x) {
    return __fdividef(2.f, 1.f + __expf(-2.f * x)) - 1.f;
}

// ---------------- pre-GEMM 1 (unchanged passing design) --------------------
template <int KDATA, int KP>
__global__ void __launch_bounds__(512, 1) gemm_pre_mma(
    const float* __restrict__ src,   // x [B][T][KDATA]
    const float* __restrict__ w,     // [256][KDATA]
    const float* __restrict__ bia, const float* __restrict__ bib)
{
    constexpr int SA = KP + 8;
    extern __shared__ __nv_bfloat16 smh[];
    __nv_bfloat16* sWH = smh;
    __nv_bfloat16* sWL = sWH + 256 * SA;
    __nv_bfloat16* sAH = sWL + 256 * SA;
    __nv_bfloat16* sAL = sAH + 128 * SA;

    const int tid = threadIdx.x;
    for (int i = tid; i < 768 * SA / 2; i += 512)
        ((uint32_t*)smh)[i] = 0u;
    __syncthreads();

    for (int idx = tid; idx < 256 * KDATA; idx += 512) {
        int j = idx / KDATA, k = idx - j * KDATA;
        __nv_bfloat16 h, l;
        split_bf16(w[idx], h, l);
        sWH[j * SA + k] = h;
        sWL[j * SA + k] = l;
    }
    if (tid < 256) {
        __nv_bfloat16 h, l;
        split_bf16(bia[tid] + bib[tid], h, l);
        sWH[tid * SA + KDATA] = h;
        sWL[tid * SA + KDATA] = l;
    }
    if (tid < 128)
        sAH[tid * SA + KDATA] = __float2bfloat16(1.0f);

    const int lane = tid & 31, wid = tid >> 5;
    const int g = lane >> 2, tg = lane & 3;
    const int wRow = (wid & 3) * 32;
    const int wCol = (wid >> 2) * 64;

    for (int tile = blockIdx.x; tile < NTILES; tile += gridDim.x) {
        const int t = tile >> 4, b0 = (tile & 15) << 7;

        __syncthreads();
        for (int idx = tid; idx < 128 * (KDATA / 2); idx += 512) {
            int m = idx / (KDATA / 2), kp = idx - m * (KDATA / 2);
            const float* rp = src + ((size_t)(b0 + m) * T + t) * KDATA;
            float2 v = *(const float2*)(rp + 2 * kp);
            __nv_bfloat16 h0, l0, h1, l1;
            split_bf16(v.x, h0, l0);
            split_bf16(v.y, h1, l1);
            sAH[m * SA + 2 * kp] = h0; sAH[m * SA + 2 * kp + 1] = h1;
            sAL[m * SA + 2 * kp] = l0; sAL[m * SA + 2 * kp + 1] = l1;
        }
        __syncthreads();

        float acc[2][8][4] = {};
        #pragma unroll
        for (int kk = 0; kk < KP / 16; ++kk) {
            uint32_t ah[2][4], al[2][4];
            #pragma unroll
            for (int f = 0; f < 2; ++f) {
                const int base = (wRow + f * 16 + g) * SA + kk * 16 + tg * 2;
                ah[f][0] = ld32bf(sAH + base);
                ah[f][1] = ld32bf(sAH + base + 8 * SA);
                ah[f][2] = ld32bf(sAH + base + 8);
                ah[f][3] = ld32bf(sAH + base + 8 * SA + 8);
                al[f][0] = ld32bf(sAL + base);
                al[f][1] = ld32bf(sAL + base + 8 * SA);
                al[f][2] = ld32bf(sAL + base + 8);
                al[f][3] = ld32bf(sAL + base + 8 * SA + 8);
            }
            #pragma unroll
            for (int n = 0; n < 8; ++n) {
                const int bbase = (wCol + n * 8 + g) * SA + kk * 16 + tg * 2;
                const uint32_t bh0 = ld32bf(sWH + bbase);
                const uint32_t bh1 = ld32bf(sWH + bbase + 8);
                const uint32_t bl0 = ld32bf(sWL + bbase);
                const uint32_t bl1 = ld32bf(sWL + bbase + 8);
                #pragma unroll
                for (int f = 0; f < 2; ++f) {
                    mma16816(acc[f][n], ah[f], bh0, bh1);
                    mma16816(acc[f][n], al[f], bh0, bh1);
                    mma16816(acc[f][n], ah[f], bl0, bl1);
                }
            }
        }

        float* orow = g_pre1 + ((size_t)t * B + b0) * G4;
        #pragma unroll
        for (int f = 0; f < 2; ++f) {
            const int r0 = wRow + f * 16 + g;
            #pragma unroll
            for (int n = 0; n < 8; ++n) {
                const int col = wCol + n * 8 + tg * 2;
                __stcs((float2*)(orow + (size_t)r0 * G4 + col),
                       make_float2(acc[f][n][0], acc[f][n][1]));
                __stcs((float2*)(orow + (size_t)(r0 + 8) * G4 + col),
                       make_float2(acc[f][n][2], acc[f][n][3]));
            }
        }
    }
}

// ---------------- fused 2-layer recurrence -------------------------------
// CTA = 16 batch, 512 threads (16 warps). Warp w owns j in [16w, 16w+16)
// for ALL three GEMMs. Step t: acc1 = Whh0@h1[t-1]; acc2 = Wih1@h1[t-1]
// + Whh1@h2[t-2]. Activation: h1[t] and (t>=1) h2[t-1]. Post-loop: h2[T-1],
// then FC head. W_hh1 frags cached in per-thread-interleaved SMEM.
__global__ void __launch_bounds__(512, 1) lstm_fused(
    const float* __restrict__ w_hh0,  // [256][64]
    const float* __restrict__ w_ih1,  // [256][64]
    const float* __restrict__ w_hh1,  // [256][64]
    const float* __restrict__ bi1,    // [256]
    const float* __restrict__ bh1,    // [256]
    const float* __restrict__ fc_w,   // [O][H]
    const float* __restrict__ fc_b,   // [O]
    float* __restrict__ out)          // [B][O]
{
    extern __shared__ uint32_t smu[];
    uint32_t* hB1h = smu;                      // [32][HBS]
    uint32_t* hB1l = smu + 768;
    uint32_t* hB2h = smu + 1536;
    uint32_t* hB2l = smu + 2304;
    uint32_t* sWD  = smu + 3072;               // [32 words][512 thr] W_hh1 frags
    float* sGate1 = (float*)(smu + 3072 + 16384);       // [256][GS]
    float* sGate2 = sGate1 + 256 * GS;                  // [256][GS]
    float* sHL    = sGate2 + 256 * GS;                  // [64][20]

    const int tid = threadIdx.x;
    const int lane = tid & 31, w = tid >> 5;
    const int g = lane >> 2, tg = lane & 3;
    const int batch0 = blockIdx.x * 16;

    for (int i = tid; i < 3072; i += 512) smu[i] = 0u;   // h buffers = 0

    // static A frags: W_hh0 (a), W_ih1 (c) in regs; W_hh1 (d) -> SMEM cache
    uint32_t a_h[4][4], a_l[4][4], c_h[4][4], c_l[4][4];
    #pragma unroll
    for (int kk = 0; kk < 4; ++kk) {
        #pragma unroll
        for (int r = 0; r < 4; ++r) {
            const int row = 16 * w + g + (r & 1) * 8;
            const int col = 16 * kk + 2 * tg + (r >> 1) * 8;
            __nv_bfloat16 h0, l0, h1, l1;
            float2 v = *(const float2*)(w_hh0 + row * 64 + col);
            split_bf16(v.x, h0, l0); split_bf16(v.y, h1, l1);
            a_h[kk][r] = packbf(h0, h1); a_l[kk][r] = packbf(l0, l1);
            float2 u = *(const float2*)(w_ih1 + row * 64 + col);
            split_bf16(u.x, h0, l0); split_bf16(u.y, h1, l1);
            c_h[kk][r] = packbf(h0, h1); c_l[kk][r] = packbf(l0, l1);
            float2 z = *(const float2*)(w_hh1 + row * 64 + col);
            split_bf16(z.x, h0, l0); split_bf16(z.y, h1, l1);
            sWD[(kk * 4 + r) * 512 + tid]        = packbf(h0, h1);
            sWD[(16 + kk * 4 + r) * 512 + tid]   = packbf(l0, l1);
        }
    }

    // activation roles: one h index, 2 batches, BOTH layers
    const int hC = tid & 63;
    const int bC = (tid >> 6) * 2;
    float c1_reg[2] = {0.f, 0.f};
    float c2_reg[2] = {0.f, 0.f};
    float bv[4];
    #pragma unroll
    for (int p = 0; p < 4; ++p)
        bv[p] = bi1[p * 64 + hC] + bh1[p * 64 + hC];
    __syncthreads();

    for (int t = 0; t < T; ++t) {
        // prefetch pre1[t] (overlaps MMA phase)
        const float* pt = g_pre1 + ((size_t)t * B + batch0) * G4;
        float pv[2][4];
        #pragma unroll
        for (int q = 0; q < 2; ++q)
            #pragma unroll
            for (int p = 0; p < 4; ++p)
                pv[q][p] = __ldcs(&pt[(bC + q) * G4 + p * 64 + hC]);

        float acc1[2][4] = {};   // gates1 rec part
        float acc2[2][4] = {};   // gates2 = Wih1@h1 + Whh1@h2
        // part 1: B = h1[t-1] feeds acc1 (W_hh0) and acc2 (W_ih1)
        #pragma unroll
        for (int kk = 0; kk < 4; ++kk) {
            #pragma unroll
            for (int nt = 0; nt < 2; ++nt) {
                const int c0 = (8 * kk + tg) * HBS + 8 * nt + g;
                const int c1 = (8 * kk + 4 + tg) * HBS + 8 * nt + g;
                const uint32_t bh0 = hB1h[c0], bh1v = hB1h[c1];
                const uint32_t bl0 = hB1l[c0], bl1v = hB1l[c1];
                mma16816(acc1[nt], a_h[kk], bh0, bh1v);
                mma16816(acc2[nt], c_h[kk], bh0, bh1v);
                mma16816(acc1[nt], a_l[kk], bh0, bh1v);
                mma16816(acc2[nt], c_l[kk], bh0, bh1v);
                mma16816(acc1[nt], a_h[kk], bl0, bl1v);
                mma16816(acc2[nt], c_h[kk], bl0, bl1v);
            }
        }
        // part 2: B = h2[t-2] feeds acc2 (W_hh1 from SMEM frag cache)
        #pragma unroll
        for (int kk = 0; kk < 4; ++kk) {
            uint32_t dh[4], dl[4];
            #pragma unroll
            for (int r = 0; r < 4; ++r) {
                dh[r] = sWD[(kk * 4 + r) * 512 + tid];
                dl[r] = sWD[(16 + kk * 4 + r) * 512 + tid];
            }
            #pragma unroll
            for (int nt = 0; nt < 2; ++nt) {
                const int c0 = (8 * kk + tg) * HBS + 8 * nt + g;
                const int c1 = (8 * kk + 4 + tg) * HBS + 8 * nt + g;
                const uint32_t bh0 = hB2h[c0], bh1v = hB2h[c1];
                const uint32_t bl0 = hB2l[c0], bl1v = hB2l[c1];
                mma16816(acc2[nt], dh, bh0, bh1v);
                mma16816(acc2[nt], dl, bh0, bh1v);
                mma16816(acc2[nt], dh, bl0, bl1v);
            }
        }
        // store gates
        #pragma unroll
        for (int nt = 0; nt < 2; ++nt) {
            *(float2*)(sGate1 + (16 * w + g) * GS + 8 * nt + 2 * tg) =
                make_float2(acc1[nt][0], acc1[nt][1]);
            *(float2*)(sGate1 + (16 * w + g + 8) * GS + 8 * nt + 2 * tg) =
                make_float2(acc1[nt][2], acc1[nt][3]);
            *(float2*)(sGate2 + (16 * w + g) * GS + 8 * nt + 2 * tg) =
                make_float2(acc2[nt][0], acc2[nt][1]);
            *(float2*)(sGate2 + (16 * w + g + 8) * GS + 8 * nt + 2 * tg) =
                make_float2(acc2[nt][2], acc2[nt][3]);
        }
        __syncthreads();   // BAR1: gates visible; hB reads done

        // activation L1: h1[t]
        float2 G[4];
        #pragma unroll
        for (int p = 0; p < 4; ++p)
            G[p] = *(const float2*)(sGate1 + (hC + 64 * p) * GS + bC);
        #pragma unroll
        for (int q = 0; q < 2; ++q) {
            float gi = (q ? G[0].y : G[0].x) + pv[q][0];
            float gf = (q ? G[1].y : G[1].x) + pv[q][1];
            float gg = (q ? G[2].y : G[2].x) + pv[q][2];
            float go = (q ? G[3].y : G[3].x) + pv[q][3];
            gi = fsig(gi); gf = fsig(gf); go = fsig(go); gg = ftanh(gg);
            const float c = gf * c1_reg[q] + gi * gg;
            c1_reg[q] = c;
            const float hv = go * ftanh(c);
            __nv_bfloat16 hh, hl;
            split_bf16(hv, hh, hl);
            const int off = ((hC >> 1) * HBS + bC + q) * 2 + (hC & 1);
            ((unsigned short*)hB1h)[off] = __bfloat16_as_ushort(hh);
            ((unsigned short*)hB1l)[off] = __bfloat16_as_ushort(hl);
        }
        // activation L2: h2[t-1] (skip at t=0)
        if (t >= 1) {
            #pragma unroll
            for (int p = 0; p < 4; ++p)
                G[p] = *(const float2*)(sGate2 + (hC + 64 * p) * GS + bC);
            #pragma unroll
            for (int q = 0; q < 2; ++q) {
                float gi = (q ? G[0].y : G[0].x) + bv[0];
                float gf = (q ? G[1].y : G[1].x) + bv[1];
                float gg = (q ? G[2].y : G[2].x) + bv[2];
                float go = (q ? G[3].y : G[3].x) + bv[3];
                gi = fsig(gi); gf = fsig(gf); go = fsig(go); gg = ftanh(gg);
                const float c = gf * c2_reg[q] + gi * gg;
                c2_reg[q] = c;
                const float hv = go * ftanh(c);
                __nv_bfloat16 hh, hl;
                split_bf16(hv, hh, hl);
                const int off = ((hC >> 1) * HBS + bC + q) * 2 + (hC & 1);
                ((unsigned short*)hB2h)[off] = __bfloat16_as_ushort(hh);
                ((unsigned short*)hB2l)[off] = __bfloat16_as_ushort(hl);
            }
        }
        __syncthreads();   // BAR2: h writes visible for next step
    }

    // epilogue step t=T: gates2[T-1] from h1[T-1], h2[T-2] -> h2[T-1]
    {
        float acc2[2][4] = {};
        #pragma unroll
        for (int kk = 0; kk < 4; ++kk) {
            uint32_t dh[4], dl[4];
            #pragma unroll
            for (int r = 0; r < 4; ++r) {
                dh[r] = sWD[(kk * 4 + r) * 512 + tid];
                dl[r] = sWD[(16 + kk * 4 + r) * 512 + tid];
            }
            #pragma unroll
            for (int nt = 0; nt < 2; ++nt) {
                const int c0 = (8 * kk + tg) * HBS + 8 * nt + g;
                const int c1 = (8 * kk + 4 + tg) * HBS + 8 * nt + g;
                uint32_t bh0 = hB1h[c0], bh1v = hB1h[c1];
                uint32_t bl0 = hB1l[c0], bl1v = hB1l[c1];
                mma16816(acc2[nt], c_h[kk], bh0, bh1v);
                mma16816(acc2[nt], c_l[kk], bh0, bh1v);
                mma16816(acc2[nt], c_h[kk], bl0, bl1v);
                bh0 = hB2h[c0]; bh1v = hB2h[c1];
                bl0 = hB2l[c0]; bl1v = hB2l[c1];
                mma16816(acc2[nt], dh, bh0, bh1v);
                mma16816(acc2[nt], dl, bh0, bh1v);
                mma16816(acc2[nt], dh, bl0, bl1v);
            }
        }
        #pragma unroll
        for (int nt = 0; nt < 2; ++nt) {
            *(float2*)(sGate2 + (16 * w + g) * GS + 8 * nt + 2 * tg) =
                make_float2(acc2[nt][0], acc2[nt][1]);
            *(float2*)(sGate2 + (16 * w + g + 8) * GS + 8 * nt + 2 * tg) =
                make_float2(acc2[nt][2], acc2[nt][3]);
        }
        __syncthreads();

        float2 G[4];
        #pragma unroll
        for (int p = 0; p < 4; ++p)
            G[p] = *(const float2*)(sGate2 + (hC + 64 * p) * GS + bC);
        #pragma unroll
        for (int q = 0; q < 2; ++q) {
            float gi = (q ? G[0].y : G[0].x) + bv[0];
            float gf = (q ? G[1].y : G[1].x) + bv[1];
            float gg = (q ? G[2].y : G[2].x) + bv[2];
            float go = (q ? G[3].y : G[3].x) + bv[3];
            gi = fsig(gi); gf = fsig(gf); go = fsig(go); gg = ftanh(gg);
            const float c = gf * c2_reg[q] + gi * gg;
            sHL[hC * 20 + bC + q] = go * ftanh(c);
        }
        __syncthreads();
    }

    // FC head: out = h2_last @ fc_w^T + fc_b
    for (int idx = tid; idx < 16 * O; idx += 512) {
        int b = idx / O, o = idx - (idx / O) * O;
        float s = fc_b[o];
        #pragma unroll
        for (int h = 0; h < H; ++h)
            s += sHL[h * 20 + b] * fc_w[o * H + h];
        out[(batch0 + b) * O + o] = s;
    }
}

extern "C" void kernel_launch(void* const* d_in, const int* in_sizes, int n_in,
                              void* d_out, int out_size) {
    const float* x     = (const float*)d_in[0];
    const float* w_ih0 = (const float*)d_in[1];
    const float* w_hh0 = (const float*)d_in[2];
    const float* b_ih0 = (const float*)d_in[3];
    const float* b_hh0 = (const float*)d_in[4];
    const float* w_ih1 = (const float*)d_in[5];
    const float* w_hh1 = (const float*)d_in[6];
    const float* b_ih1 = (const float*)d_in[7];
    const float* b_hh1 = (const float*)d_in[8];
    const float* fc_w  = (const float*)d_in[9];
    const float* fc_b  = (const float*)d_in[10];
    float* out = (float*)d_out;

    const int smG1 = 768 * (96 + 8) * 2;    // 159744 B
    // fused rec smem: 3072(hB) + 16384(WD frags) + 2*256*GS + 64*20 words
    const int smR = (3072 + 16384 + 2 * 256 * GS + 64 * 20) * 4 + 256;

    cudaFuncSetAttribute(gemm_pre_mma<88, 96>,
                         cudaFuncAttributeMaxDynamicSharedMemorySize, smG1);
    cudaFuncSetAttribute(lstm_fused,
                         cudaFuncAttributeMaxDynamicSharedMemorySize, smR);

    gemm_pre_mma<88, 96><<<148, 512, smG1>>>(x, w_ih0, b_ih0, b_hh0);
    lstm_fused<<<B / 16, 512, smR>>>(
        w_hh0, w_ih1, w_hh1, b_ih1, b_hh1, fc_w, fc_b, out);
}

// round 11
// speedup vs baseline: 5.7613x; 1.2810x over previous
#include <cuda_runtime.h>
#include <cuda_fp16.h>
#include <cstdint>
#include <math.h>

// MusicRNN: 2-layer LSTM (B=2048, T=256, I=88, H=64) + FC (O=13).
// R10: precision scheme switched from 3-term split-bf16 to 2-TERM fp16:
// static operand (weights) split hi+lo fp16 (~22-bit exact), dynamic operand
// (x / h) rounded to single fp16 (2^-12 rel err -> predicted final ~1e-4).
// Cuts HMMA count by 1/3, halves h-buffer LDS traffic and gemm1 staging.
// Structure from R9: gemm1 -> fused 2-layer rec (+FC head).

namespace {
constexpr int B = 2048, T = 256, I = 88, H = 64, O = 13, G4 = 256;
constexpr int NTILES = T * (B / 128);       // 4096 tiles of 128 rows
constexpr int HBS = 24;                      // hB row stride (words)
constexpr int GS  = 22;                      // sGate row stride (floats)
}

// scratch (static __device__: allocation-free rule)
__device__ float g_pre1[(size_t)T * B * G4];   // 512 MB: x @ W_ih0^T + bias0

// ---------------- warp-MMA fp16 (baseline PTX, works on .target sm_103) ----
__device__ __forceinline__ void mma16816(float* c, const uint32_t* a,
                                         uint32_t b0, uint32_t b1) {
    asm volatile(
        "mma.sync.aligned.m16n8k16.row.col.f32.f16.f16.f32 "
        "{%0,%1,%2,%3}, {%4,%5,%6,%7}, {%8,%9}, {%0,%1,%2,%3};"
        : "+f"(c[0]), "+f"(c[1]), "+f"(c[2]), "+f"(c[3])
        : "r"(a[0]), "r"(a[1]), "r"(a[2]), "r"(a[3]), "r"(b0), "r"(b1));
}
__device__ __forceinline__ uint32_t ld32h(const __half* p) {
    return *(const uint32_t*)p;
}
__device__ __forceinline__ void split_f16(float v, __half& h, __half& l) {
    h = __float2half_rn(v);
    l = __float2half_rn(v - __half2float(h));
}
__device__ __forceinline__ uint32_t packh(__half a, __half b) {
    return (uint32_t)__half_as_ushort(a) | ((uint32_t)__half_as_ushort(b) << 16);
}
__device__ __forceinline__ float fsig(float x) {
    return __fdividef(1.f, 1.f + __expf(-x));
}
__device__ __forceinline__ float ftanh(float x) {
    return __fdividef(2.f, 1.f + __expf(-2.f * x)) - 1.f;
}

// ---------------- pre-GEMM 1: pre1 = x @ W_ih0^T + bias0 -------------------
// A = x rounded to fp16 (single buffer), B = W split hi/lo fp16 in smem.
// 2 MMAs per (k-step, n-tile, m-frag). Bias folded as extra K column.
template <int KDATA, int KP>
__global__ void __launch_bounds__(512, 1) gemm_pre_mma(
    const float* __restrict__ src,   // x [B][T][KDATA]
    const float* __restrict__ w,     // [256][KDATA]
    const float* __restrict__ bia, const float* __restrict__ bib)
{
    constexpr int SA = KP + 8;   // row stride in halves
    extern __shared__ __half smh[];
    __half* sWH = smh;                 // [256][SA]
    __half* sWL = sWH + 256 * SA;      // [256][SA]
    __half* sA  = sWL + 256 * SA;      // [128][SA]  x (single fp16)

    const int tid = threadIdx.x;
    for (int i = tid; i < 640 * SA / 2; i += 512)
        ((uint32_t*)smh)[i] = 0u;
    __syncthreads();

    for (int idx = tid; idx < 256 * KDATA; idx += 512) {
        int j = idx / KDATA, k = idx - j * KDATA;
        __half h, l;
        split_f16(w[idx], h, l);
        sWH[j * SA + k] = h;
        sWL[j * SA + k] = l;
    }
    if (tid < 256) {
        __half h, l;
        split_f16(bia[tid] + bib[tid], h, l);
        sWH[tid * SA + KDATA] = h;
        sWL[tid * SA + KDATA] = l;
    }
    if (tid < 128)
        sA[tid * SA + KDATA] = __float2half_rn(1.0f);  // ones col (exact)

    const int lane = tid & 31, wid = tid >> 5;
    const int g = lane >> 2, tg = lane & 3;
    const int wRow = (wid & 3) * 32;
    const int wCol = (wid >> 2) * 64;

    for (int tile = blockIdx.x; tile < NTILES; tile += gridDim.x) {
        const int t = tile >> 4, b0 = (tile & 15) << 7;

        __syncthreads();
        for (int idx = tid; idx < 128 * (KDATA / 2); idx += 512) {
            int m = idx / (KDATA / 2), kp = idx - m * (KDATA / 2);
            const float* rp = src + ((size_t)(b0 + m) * T + t) * KDATA;
            float2 v = *(const float2*)(rp + 2 * kp);
            __half2 hp;
            hp.x = __float2half_rn(v.x);
            hp.y = __float2half_rn(v.y);
            *(__half2*)(sA + m * SA + 2 * kp) = hp;
        }
        __syncthreads();

        float acc[2][8][4] = {};
        #pragma unroll
        for (int kk = 0; kk < KP / 16; ++kk) {
            uint32_t ah[2][4];
            #pragma unroll
            for (int f = 0; f < 2; ++f) {
                const int base = (wRow + f * 16 + g) * SA + kk * 16 + tg * 2;
                ah[f][0] = ld32h(sA + base);
                ah[f][1] = ld32h(sA + base + 8 * SA);
                ah[f][2] = ld32h(sA + base + 8);
                ah[f][3] = ld32h(sA + base + 8 * SA + 8);
            }
            #pragma unroll
            for (int n = 0; n < 8; ++n) {
                const int bbase = (wCol + n * 8 + g) * SA + kk * 16 + tg * 2;
                const uint32_t bh0 = ld32h(sWH + bbase);
                const uint32_t bh1 = ld32h(sWH + bbase + 8);
                const uint32_t bl0 = ld32h(sWL + bbase);
                const uint32_t bl1 = ld32h(sWL + bbase + 8);
                #pragma unroll
                for (int f = 0; f < 2; ++f) {
                    mma16816(acc[f][n], ah[f], bh0, bh1);
                    mma16816(acc[f][n], ah[f], bl0, bl1);
                }
            }
        }

        float* orow = g_pre1 + ((size_t)t * B + b0) * G4;
        #pragma unroll
        for (int f = 0; f < 2; ++f) {
            const int r0 = wRow + f * 16 + g;
            #pragma unroll
            for (int n = 0; n < 8; ++n) {
                const int col = wCol + n * 8 + tg * 2;
                __stcs((float2*)(orow + (size_t)r0 * G4 + col),
                       make_float2(acc[f][n][0], acc[f][n][1]));
                __stcs((float2*)(orow + (size_t)(r0 + 8) * G4 + col),
                       make_float2(acc[f][n][2], acc[f][n][3]));
            }
        }
    }
}

// ---------------- fused 2-layer recurrence (fp16, 2-term) ------------------
// CTA = 16 batch, 512 threads. Step t: acc1 = Whh0@h1[t-1];
// acc2 = Wih1@h1[t-1] + Whh1@h2[t-2]. h stored as SINGLE fp16 in smem;
// weights split hi/lo (Whh0, Wih1 in regs; Whh1 in per-thread SMEM cache).
__global__ void __launch_bounds__(512, 1) lstm_fused(
    const float* __restrict__ w_hh0,  // [256][64]
    const float* __restrict__ w_ih1,  // [256][64]
    const float* __restrict__ w_hh1,  // [256][64]
    const float* __restrict__ bi1,    // [256]
    const float* __restrict__ bh1,    // [256]
    const float* __restrict__ fc_w,   // [O][H]
    const float* __restrict__ fc_b,   // [O]
    float* __restrict__ out)          // [B][O]
{
    extern __shared__ uint32_t smu[];
    uint32_t* hB1 = smu;                       // [32][HBS] h1 fp16 pairs
    uint32_t* hB2 = smu + 768;                 // [32][HBS] h2 fp16 pairs
    uint32_t* sWD = smu + 1536;                // [32 words][512] W_hh1 frags
    float* sGate1 = (float*)(smu + 1536 + 16384);   // [256][GS]
    float* sGate2 = sGate1 + 256 * GS;              // [256][GS]
    float* sHL    = sGate2 + 256 * GS;              // [64][20]

    const int tid = threadIdx.x;
    const int lane = tid & 31, w = tid >> 5;
    const int g = lane >> 2, tg = lane & 3;
    const int batch0 = blockIdx.x * 16;

    for (int i = tid; i < 1536; i += 512) smu[i] = 0u;   // h buffers = 0

    // static A frags: W_hh0 (a), W_ih1 (c) in regs; W_hh1 (d) -> SMEM cache
    uint32_t a_h[4][4], a_l[4][4], c_h[4][4], c_l[4][4];
    #pragma unroll
    for (int kk = 0; kk < 4; ++kk) {
        #pragma unroll
        for (int r = 0; r < 4; ++r) {
            const int row = 16 * w + g + (r & 1) * 8;
            const int col = 16 * kk + 2 * tg + (r >> 1) * 8;
            __half h0, l0, h1, l1;
            float2 v = *(const float2*)(w_hh0 + row * 64 + col);
            split_f16(v.x, h0, l0); split_f16(v.y, h1, l1);
            a_h[kk][r] = packh(h0, h1); a_l[kk][r] = packh(l0, l1);
            float2 u = *(const float2*)(w_ih1 + row * 64 + col);
            split_f16(u.x, h0, l0); split_f16(u.y, h1, l1);
            c_h[kk][r] = packh(h0, h1); c_l[kk][r] = packh(l0, l1);
            float2 z = *(const float2*)(w_hh1 + row * 64 + col);
            split_f16(z.x, h0, l0); split_f16(z.y, h1, l1);
            sWD[(kk * 4 + r) * 512 + tid]      = packh(h0, h1);
            sWD[(16 + kk * 4 + r) * 512 + tid] = packh(l0, l1);
        }
    }

    const int hC = tid & 63;
    const int bC = (tid >> 6) * 2;
    float c1_reg[2] = {0.f, 0.f};
    float c2_reg[2] = {0.f, 0.f};
    float bv[4];
    #pragma unroll
    for (int p = 0; p < 4; ++p)
        bv[p] = bi1[p * 64 + hC] + bh1[p * 64 + hC];
    __syncthreads();

    for (int t = 0; t < T; ++t) {
        // prefetch pre1[t] (overlaps MMA phase)
        const float* pt = g_pre1 + ((size_t)t * B + batch0) * G4;
        float pv[2][4];
        #pragma unroll
        for (int q = 0; q < 2; ++q)
            #pragma unroll
            for (int p = 0; p < 4; ++p)
                pv[q][p] = __ldcs(&pt[(bC + q) * G4 + p * 64 + hC]);

        float acc1[2][4] = {};   // gates1 rec part
        float acc2[2][4] = {};   // gates2 = Wih1@h1 + Whh1@h2
        // part 1: B = h1[t-1] feeds acc1 (W_hh0 2-term) and acc2 (W_ih1 2-term)
        #pragma unroll
        for (int kk = 0; kk < 4; ++kk) {
            #pragma unroll
            for (int nt = 0; nt < 2; ++nt) {
                const int c0 = (8 * kk + tg) * HBS + 8 * nt + g;
                const int c1 = (8 * kk + 4 + tg) * HBS + 8 * nt + g;
                const uint32_t b0 = hB1[c0], b1 = hB1[c1];
                mma16816(acc1[nt], a_h[kk], b0, b1);
                mma16816(acc2[nt], c_h[kk], b0, b1);
                mma16816(acc1[nt], a_l[kk], b0, b1);
                mma16816(acc2[nt], c_l[kk], b0, b1);
            }
        }
        // part 2: B = h2[t-2] feeds acc2 (W_hh1 2-term from SMEM frag cache)
        #pragma unroll
        for (int kk = 0; kk < 4; ++kk) {
            uint32_t dh[4], dl[4];
            #pragma unroll
            for (int r = 0; r < 4; ++r) {
                dh[r] = sWD[(kk * 4 + r) * 512 + tid];
                dl[r] = sWD[(16 + kk * 4 + r) * 512 + tid];
            }
            #pragma unroll
            for (int nt = 0; nt < 2; ++nt) {
                const int c0 = (8 * kk + tg) * HBS + 8 * nt + g;
                const int c1 = (8 * kk + 4 + tg) * HBS + 8 * nt + g;
                const uint32_t b0 = hB2[c0], b1 = hB2[c1];
                mma16816(acc2[nt], dh, b0, b1);
                mma16816(acc2[nt], dl, b0, b1);
            }
        }
        // store gates
        #pragma unroll
        for (int nt = 0; nt < 2; ++nt) {
            *(float2*)(sGate1 + (16 * w + g) * GS + 8 * nt + 2 * tg) =
                make_float2(acc1[nt][0], acc1[nt][1]);
            *(float2*)(sGate1 + (16 * w + g + 8) * GS + 8 * nt + 2 * tg) =
                make_float2(acc1[nt][2], acc1[nt][3]);
            *(float2*)(sGate2 + (16 * w + g) * GS + 8 * nt + 2 * tg) =
                make_float2(acc2[nt][0], acc2[nt][1]);
            *(float2*)(sGate2 + (16 * w + g + 8) * GS + 8 * nt + 2 * tg) =
                make_float2(acc2[nt][2], acc2[nt][3]);
        }
        __syncthreads();   // BAR1: gates visible; hB reads done

        // activation L1: h1[t]
        float2 G[4];
        #pragma unroll
        for (int p = 0; p < 4; ++p)
            G[p] = *(const float2*)(sGate1 + (hC + 64 * p) * GS + bC);
        #pragma unroll
        for (int q = 0; q < 2; ++q) {
            float gi = (q ? G[0].y : G[0].x) + pv[q][0];
            float gf = (q ? G[1].y : G[1].x) + pv[q][1];
            float gg = (q ? G[2].y : G[2].x) + pv[q][2];
            float go = (q ? G[3].y : G[3].x) + pv[q][3];
            gi = fsig(gi); gf = fsig(gf); go = fsig(go); gg = ftanh(gg);
            const float c = gf * c1_reg[q] + gi * gg;
            c1_reg[q] = c;
            const float hv = go * ftanh(c);
            const int off = ((hC >> 1) * HBS + bC + q) * 2 + (hC & 1);
            ((unsigned short*)hB1)[off] =
                __half_as_ushort(__float2half_rn(hv));
        }
        // activation L2: h2[t-1] (skip at t=0)
        if (t >= 1) {
            #pragma unroll
            for (int p = 0; p < 4; ++p)
                G[p] = *(const float2*)(sGate2 + (hC + 64 * p) * GS + bC);
            #pragma unroll
            for (int q = 0; q < 2; ++q) {
                float gi = (q ? G[0].y : G[0].x) + bv[0];
                float gf = (q ? G[1].y : G[1].x) + bv[1];
                float gg = (q ? G[2].y : G[2].x) + bv[2];
                float go = (q ? G[3].y : G[3].x) + bv[3];
                gi = fsig(gi); gf = fsig(gf); go = fsig(go); gg = ftanh(gg);
                const float c = gf * c2_reg[q] + gi * gg;
                c2_reg[q] = c;
                const float hv = go * ftanh(c);
                const int off = ((hC >> 1) * HBS + bC + q) * 2 + (hC & 1);
                ((unsigned short*)hB2)[off] =
                    __half_as_ushort(__float2half_rn(hv));
            }
        }
        __syncthreads();   // BAR2: h writes visible for next step
    }

    // epilogue step t=T: gates2[T-1] from h1[T-1], h2[T-2] -> h2[T-1]
    {
        float acc2[2][4] = {};
        #pragma unroll
        for (int kk = 0; kk < 4; ++kk) {
            uint32_t dh[4], dl[4];
            #pragma unroll
            for (int r = 0; r < 4; ++r) {
                dh[r] = sWD[(kk * 4 + r) * 512 + tid];
                dl[r] = sWD[(16 + kk * 4 + r) * 512 + tid];
            }
            #pragma unroll
            for (int nt = 0; nt < 2; ++nt) {
                const int c0 = (8 * kk + tg) * HBS + 8 * nt + g;
                const int c1 = (8 * kk + 4 + tg) * HBS + 8 * nt + g;
                uint32_t b0 = hB1[c0], b1 = hB1[c1];
                mma16816(acc2[nt], c_h[kk], b0, b1);
                mma16816(acc2[nt], c_l[kk], b0, b1);
                b0 = hB2[c0]; b1 = hB2[c1];
                mma16816(acc2[nt], dh, b0, b1);
                mma16816(acc2[nt], dl, b0, b1);
            }
        }
        #pragma unroll
        for (int nt = 0; nt < 2; ++nt) {
            *(float2*)(sGate2 + (16 * w + g) * GS + 8 * nt + 2 * tg) =
                make_float2(acc2[nt][0], acc2[nt][1]);
            *(float2*)(sGate2 + (16 * w + g + 8) * GS + 8 * nt + 2 * tg) =
                make_float2(acc2[nt][2], acc2[nt][3]);
        }
        __syncthreads();

        float2 G[4];
        #pragma unroll
        for (int p = 0; p < 4; ++p)
            G[p] = *(const float2*)(sGate2 + (hC + 64 * p) * GS + bC);
        #pragma unroll
        for (int q = 0; q < 2; ++q) {
            float gi = (q ? G[0].y : G[0].x) + bv[0];
            float gf = (q ? G[1].y : G[1].x) + bv[1];
            float gg = (q ? G[2].y : G[2].x) + bv[2];
            float go = (q ? G[3].y : G[3].x) + bv[3];
            gi = fsig(gi); gf = fsig(gf); go = fsig(go); gg = ftanh(gg);
            const float c = gf * c2_reg[q] + gi * gg;
            sHL[hC * 20 + bC + q] = go * ftanh(c);
        }
        __syncthreads();
    }

    // FC head: out = h2_last @ fc_w^T + fc_b
    for (int idx = tid; idx < 16 * O; idx += 512) {
        int b = idx / O, o = idx - (idx / O) * O;
        float s = fc_b[o];
        #pragma unroll
        for (int h = 0; h < H; ++h)
            s += sHL[h * 20 + b] * fc_w[o * H + h];
        out[(batch0 + b) * O + o] = s;
    }
}

extern "C" void kernel_launch(void* const* d_in, const int* in_sizes, int n_in,
                              void* d_out, int out_size) {
    const float* x     = (const float*)d_in[0];
    const float* w_ih0 = (const float*)d_in[1];
    const float* w_hh0 = (const float*)d_in[2];
    const float* b_ih0 = (const float*)d_in[3];
    const float* b_hh0 = (const float*)d_in[4];
    const float* w_ih1 = (const float*)d_in[5];
    const float* w_hh1 = (const float*)d_in[6];
    const float* b_ih1 = (const float*)d_in[7];
    const float* b_hh1 = (const float*)d_in[8];
    const float* fc_w  = (const float*)d_in[9];
    const float* fc_b  = (const float*)d_in[10];
    float* out = (float*)d_out;

    const int smG1 = 640 * (96 + 8) * 2;    // 133120 B
    const int smR = (1536 + 16384 + 2 * 256 * GS + 64 * 20) * 4 + 256;

    cudaFuncSetAttribute(gemm_pre_mma<88, 96>,
                         cudaFuncAttributeMaxDynamicSharedMemorySize, smG1);
    cudaFuncSetAttribute(lstm_fused,
                         cudaFuncAttributeMaxDynamicSharedMemorySize, smR);

    gemm_pre_mma<88, 96><<<148, 512, smG1>>>(x, w_ih0, b_ih0, b_hh0);
    lstm_fused<<<B / 16, 512, smR>>>(
        w_hh0, w_ih1, w_hh1, b_ih1, b_hh1, fc_w, fc_b, out);
}

// round 12
// speedup vs baseline: 6.4043x; 1.1116x over previous
#include <cuda_runtime.h>
#include <cuda_fp16.h>
#include <cstdint>
#include <math.h>

// MusicRNN: 2-layer LSTM (B=2048, T=256, I=88, H=64) + FC (O=13).
// R11 (on top of R10's 2-term fp16 scheme):
//  - activations via tanh.approx.f32 (sigmoid = 0.5*tanh(x/2)+0.5):
//    5 MUFU/cell instead of ~10 -> ~640 cyc/SMSP/step saved in rec.
//  - g_pre1 stored as fp16: halves gemm1 store traffic (512->256MB) and
//    rec's additive-input read traffic.
// Structure: gemm1 -> fused 2-layer rec (+FC head).

namespace {
constexpr int B = 2048, T = 256, I = 88, H = 64, O = 13, G4 = 256;
constexpr int NTILES = T * (B / 128);       // 4096 tiles of 128 rows
constexpr int HBS = 24;                      // hB row stride (words)
constexpr int GS  = 22;                      // sGate row stride (floats)
}

// scratch (static __device__: allocation-free rule)
__device__ __half g_pre1[(size_t)T * B * G4];   // 256 MB: x @ W_ih0^T + bias0

// ---------------- warp-MMA fp16 (baseline PTX, works on .target sm_103) ----
__device__ __forceinline__ void mma16816(float* c, const uint32_t* a,
                                         uint32_t b0, uint32_t b1) {
    asm volatile(
        "mma.sync.aligned.m16n8k16.row.col.f32.f16.f16.f32 "
        "{%0,%1,%2,%3}, {%4,%5,%6,%7}, {%8,%9}, {%0,%1,%2,%3};"
        : "+f"(c[0]), "+f"(c[1]), "+f"(c[2]), "+f"(c[3])
        : "r"(a[0]), "r"(a[1]), "r"(a[2]), "r"(a[3]), "r"(b0), "r"(b1));
}
__device__ __forceinline__ uint32_t ld32h(const __half* p) {
    return *(const uint32_t*)p;
}
__device__ __forceinline__ void split_f16(float v, __half& h, __half& l) {
    h = __float2half_rn(v);
    l = __float2half_rn(v - __half2float(h));
}
__device__ __forceinline__ uint32_t packh(__half a, __half b) {
    return (uint32_t)__half_as_ushort(a) | ((uint32_t)__half_as_ushort(b) << 16);
}
// HW tanh (sm_75+ baseline PTX). abs err ~5e-4: same order as fp16-h rounding.
__device__ __forceinline__ float ftanh(float x) {
    float y; asm("tanh.approx.f32 %0, %1;" : "=f"(y) : "f"(x)); return y;
}
__device__ __forceinline__ float fsig(float x) {
    float y; asm("tanh.approx.f32 %0, %1;" : "=f"(y) : "f"(0.5f * x));
    return fmaf(0.5f, y, 0.5f);
}

// ---------------- pre-GEMM 1: pre1 = x @ W_ih0^T + bias0 (fp16 out) --------
template <int KDATA, int KP>
__global__ void __launch_bounds__(512, 1) gemm_pre_mma(
    const float* __restrict__ src,   // x [B][T][KDATA]
    const float* __restrict__ w,     // [256][KDATA]
    const float* __restrict__ bia, const float* __restrict__ bib)
{
    constexpr int SA = KP + 8;   // row stride in halves
    extern __shared__ __half smh[];
    __half* sWH = smh;                 // [256][SA]
    __half* sWL = sWH + 256 * SA;      // [256][SA]
    __half* sA  = sWL + 256 * SA;      // [128][SA]  x (single fp16)

    const int tid = threadIdx.x;
    for (int i = tid; i < 640 * SA / 2; i += 512)
        ((uint32_t*)smh)[i] = 0u;
    __syncthreads();

    for (int idx = tid; idx < 256 * KDATA; idx += 512) {
        int j = idx / KDATA, k = idx - j * KDATA;
        __half h, l;
        split_f16(w[idx], h, l);
        sWH[j * SA + k] = h;
        sWL[j * SA + k] = l;
    }
    if (tid < 256) {
        __half h, l;
        split_f16(bia[tid] + bib[tid], h, l);
        sWH[tid * SA + KDATA] = h;
        sWL[tid * SA + KDATA] = l;
    }
    if (tid < 128)
        sA[tid * SA + KDATA] = __float2half_rn(1.0f);  // ones col (exact)

    const int lane = tid & 31, wid = tid >> 5;
    const int g = lane >> 2, tg = lane & 3;
    const int wRow = (wid & 3) * 32;
    const int wCol = (wid >> 2) * 64;

    for (int tile = blockIdx.x; tile < NTILES; tile += gridDim.x) {
        const int t = tile >> 4, b0 = (tile & 15) << 7;

        __syncthreads();
        for (int idx = tid; idx < 128 * (KDATA / 2); idx += 512) {
            int m = idx / (KDATA / 2), kp = idx - m * (KDATA / 2);
            const float* rp = src + ((size_t)(b0 + m) * T + t) * KDATA;
            float2 v = *(const float2*)(rp + 2 * kp);
            __half2 hp;
            hp.x = __float2half_rn(v.x);
            hp.y = __float2half_rn(v.y);
            *(__half2*)(sA + m * SA + 2 * kp) = hp;
        }
        __syncthreads();

        float acc[2][8][4] = {};
        #pragma unroll
        for (int kk = 0; kk < KP / 16; ++kk) {
            uint32_t ah[2][4];
            #pragma unroll
            for (int f = 0; f < 2; ++f) {
                const int base = (wRow + f * 16 + g) * SA + kk * 16 + tg * 2;
                ah[f][0] = ld32h(sA + base);
                ah[f][1] = ld32h(sA + base + 8 * SA);
                ah[f][2] = ld32h(sA + base + 8);
                ah[f][3] = ld32h(sA + base + 8 * SA + 8);
            }
            #pragma unroll
            for (int n = 0; n < 8; ++n) {
                const int bbase = (wCol + n * 8 + g) * SA + kk * 16 + tg * 2;
                const uint32_t bh0 = ld32h(sWH + bbase);
                const uint32_t bh1 = ld32h(sWH + bbase + 8);
                const uint32_t bl0 = ld32h(sWL + bbase);
                const uint32_t bl1 = ld32h(sWL + bbase + 8);
                #pragma unroll
                for (int f = 0; f < 2; ++f) {
                    mma16816(acc[f][n], ah[f], bh0, bh1);
                    mma16816(acc[f][n], ah[f], bl0, bl1);
                }
            }
        }

        // fp16 epilogue: 2 adjacent cols pack into one u32 store
        __half* orow = g_pre1 + ((size_t)t * B + b0) * G4;
        #pragma unroll
        for (int f = 0; f < 2; ++f) {
            const int r0 = wRow + f * 16 + g;
            #pragma unroll
            for (int n = 0; n < 8; ++n) {
                const int col = wCol + n * 8 + tg * 2;
                __stcs((uint32_t*)(orow + (size_t)r0 * G4 + col),
                       packh(__float2half_rn(acc[f][n][0]),
                             __float2half_rn(acc[f][n][1])));
                __stcs((uint32_t*)(orow + (size_t)(r0 + 8) * G4 + col),
                       packh(__float2half_rn(acc[f][n][2]),
                             __float2half_rn(acc[f][n][3])));
            }
        }
    }
}

// ---------------- fused 2-layer recurrence (fp16, 2-term) ------------------
__global__ void __launch_bounds__(512, 1) lstm_fused(
    const float* __restrict__ w_hh0,  // [256][64]
    const float* __restrict__ w_ih1,  // [256][64]
    const float* __restrict__ w_hh1,  // [256][64]
    const float* __restrict__ bi1,    // [256]
    const float* __restrict__ bh1,    // [256]
    const float* __restrict__ fc_w,   // [O][H]
    const float* __restrict__ fc_b,   // [O]
    float* __restrict__ out)          // [B][O]
{
    extern __shared__ uint32_t smu[];
    uint32_t* hB1 = smu;                       // [32][HBS] h1 fp16 pairs
    uint32_t* hB2 = smu + 768;                 // [32][HBS] h2 fp16 pairs
    uint32_t* sWD = smu + 1536;                // [32 words][512] W_hh1 frags
    float* sGate1 = (float*)(smu + 1536 + 16384);   // [256][GS]
    float* sGate2 = sGate1 + 256 * GS;              // [256][GS]
    float* sHL    = sGate2 + 256 * GS;              // [64][20]

    const int tid = threadIdx.x;
    const int lane = tid & 31, w = tid >> 5;
    const int g = lane >> 2, tg = lane & 3;
    const int batch0 = blockIdx.x * 16;

    for (int i = tid; i < 1536; i += 512) smu[i] = 0u;   // h buffers = 0

    // static A frags: W_hh0 (a), W_ih1 (c) in regs; W_hh1 (d) -> SMEM cache
    uint32_t a_h[4][4], a_l[4][4], c_h[4][4], c_l[4][4];
    #pragma unroll
    for (int kk = 0; kk < 4; ++kk) {
        #pragma unroll
        for (int r = 0; r < 4; ++r) {
            const int row = 16 * w + g + (r & 1) * 8;
            const int col = 16 * kk + 2 * tg + (r >> 1) * 8;
            __half h0, l0, h1, l1;
            float2 v = *(const float2*)(w_hh0 + row * 64 + col);
            split_f16(v.x, h0, l0); split_f16(v.y, h1, l1);
            a_h[kk][r] = packh(h0, h1); a_l[kk][r] = packh(l0, l1);
            float2 u = *(const float2*)(w_ih1 + row * 64 + col);
            split_f16(u.x, h0, l0); split_f16(u.y, h1, l1);
            c_h[kk][r] = packh(h0, h1); c_l[kk][r] = packh(l0, l1);
            float2 z = *(const float2*)(w_hh1 + row * 64 + col);
            split_f16(z.x, h0, l0); split_f16(z.y, h1, l1);
            sWD[(kk * 4 + r) * 512 + tid]      = packh(h0, h1);
            sWD[(16 + kk * 4 + r) * 512 + tid] = packh(l0, l1);
        }
    }

    const int hC = tid & 63;
    const int bC = (tid >> 6) * 2;
    float c1_reg[2] = {0.f, 0.f};
    float c2_reg[2] = {0.f, 0.f};
    float bv[4];
    #pragma unroll
    for (int p = 0; p < 4; ++p)
        bv[p] = bi1[p * 64 + hC] + bh1[p * 64 + hC];
    __syncthreads();

    for (int t = 0; t < T; ++t) {
        // prefetch pre1[t] fp16 (overlaps MMA phase)
        const __half* pt = g_pre1 + ((size_t)t * B + batch0) * G4;
        float pv[2][4];
        #pragma unroll
        for (int q = 0; q < 2; ++q)
            #pragma unroll
            for (int p = 0; p < 4; ++p) {
                unsigned short us =
                    __ldcs((const unsigned short*)(pt + (bC + q) * G4 + p * 64 + hC));
                pv[q][p] = __half2float(__ushort_as_half(us));
            }

        float acc1[2][4] = {};   // gates1 rec part
        float acc2[2][4] = {};   // gates2 = Wih1@h1 + Whh1@h2
        // part 1: B = h1[t-1] feeds acc1 (W_hh0) and acc2 (W_ih1)
        #pragma unroll
        for (int kk = 0; kk < 4; ++kk) {
            #pragma unroll
            for (int nt = 0; nt < 2; ++nt) {
                const int c0 = (8 * kk + tg) * HBS + 8 * nt + g;
                const int c1 = (8 * kk + 4 + tg) * HBS + 8 * nt + g;
                const uint32_t b0 = hB1[c0], b1 = hB1[c1];
                mma16816(acc1[nt], a_h[kk], b0, b1);
                mma16816(acc2[nt], c_h[kk], b0, b1);
                mma16816(acc1[nt], a_l[kk], b0, b1);
                mma16816(acc2[nt], c_l[kk], b0, b1);
            }
        }
        // part 2: B = h2[t-2] feeds acc2 (W_hh1 from SMEM frag cache)
        #pragma unroll
        for (int kk = 0; kk < 4; ++kk) {
            uint32_t dh[4], dl[4];
            #pragma unroll
            for (int r = 0; r < 4; ++r) {
                dh[r] = sWD[(kk * 4 + r) * 512 + tid];
                dl[r] = sWD[(16 + kk * 4 + r) * 512 + tid];
            }
            #pragma unroll
            for (int nt = 0; nt < 2; ++nt) {
                const int c0 = (8 * kk + tg) * HBS + 8 * nt + g;
                const int c1 = (8 * kk + 4 + tg) * HBS + 8 * nt + g;
                const uint32_t b0 = hB2[c0], b1 = hB2[c1];
                mma16816(acc2[nt], dh, b0, b1);
                mma16816(acc2[nt], dl, b0, b1);
            }
        }
        // store gates
        #pragma unroll
        for (int nt = 0; nt < 2; ++nt) {
            *(float2*)(sGate1 + (16 * w + g) * GS + 8 * nt + 2 * tg) =
                make_float2(acc1[nt][0], acc1[nt][1]);
            *(float2*)(sGate1 + (16 * w + g + 8) * GS + 8 * nt + 2 * tg) =
                make_float2(acc1[nt][2], acc1[nt][3]);
            *(float2*)(sGate2 + (16 * w + g) * GS + 8 * nt + 2 * tg) =
                make_float2(acc2[nt][0], acc2[nt][1]);
            *(float2*)(sGate2 + (16 * w + g + 8) * GS + 8 * nt + 2 * tg) =
                make_float2(acc2[nt][2], acc2[nt][3]);
        }
        __syncthreads();   // BAR1: gates visible; hB reads done

        // activation L1: h1[t]
        float2 G[4];
        #pragma unroll
        for (int p = 0; p < 4; ++p)
            G[p] = *(const float2*)(sGate1 + (hC + 64 * p) * GS + bC);
        #pragma unroll
        for (int q = 0; q < 2; ++q) {
            float gi = (q ? G[0].y : G[0].x) + pv[q][0];
            float gf = (q ? G[1].y : G[1].x) + pv[q][1];
            float gg = (q ? G[2].y : G[2].x) + pv[q][2];
            float go = (q ? G[3].y : G[3].x) + pv[q][3];
            gi = fsig(gi); gf = fsig(gf); go = fsig(go); gg = ftanh(gg);
            const float c = gf * c1_reg[q] + gi * gg;
            c1_reg[q] = c;
            const float hv = go * ftanh(c);
            const int off = ((hC >> 1) * HBS + bC + q) * 2 + (hC & 1);
            ((unsigned short*)hB1)[off] =
                __half_as_ushort(__float2half_rn(hv));
        }
        // activation L2: h2[t-1] (skip at t=0)
        if (t >= 1) {
            #pragma unroll
            for (int p = 0; p < 4; ++p)
                G[p] = *(const float2*)(sGate2 + (hC + 64 * p) * GS + bC);
            #pragma unroll
            for (int q = 0; q < 2; ++q) {
                float gi = (q ? G[0].y : G[0].x) + bv[0];
                float gf = (q ? G[1].y : G[1].x) + bv[1];
                float gg = (q ? G[2].y : G[2].x) + bv[2];
                float go = (q ? G[3].y : G[3].x) + bv[3];
                gi = fsig(gi); gf = fsig(gf); go = fsig(go); gg = ftanh(gg);
                const float c = gf * c2_reg[q] + gi * gg;
                c2_reg[q] = c;
                const float hv = go * ftanh(c);
                const int off = ((hC >> 1) * HBS + bC + q) * 2 + (hC & 1);
                ((unsigned short*)hB2)[off] =
                    __half_as_ushort(__float2half_rn(hv));
            }
        }
        __syncthreads();   // BAR2: h writes visible for next step
    }

    // epilogue step t=T: gates2[T-1] from h1[T-1], h2[T-2] -> h2[T-1]
    {
        float acc2[2][4] = {};
        #pragma unroll
        for (int kk = 0; kk < 4; ++kk) {
            uint32_t dh[4], dl[4];
            #pragma unroll
            for (int r = 0; r < 4; ++r) {
                dh[r] = sWD[(kk * 4 + r) * 512 + tid];
                dl[r] = sWD[(16 + kk * 4 + r) * 512 + tid];
            }
            #pragma unroll
            for (int nt = 0; nt < 2; ++nt) {
                const int c0 = (8 * kk + tg) * HBS + 8 * nt + g;
                const int c1 = (8 * kk + 4 + tg) * HBS + 8 * nt + g;
                uint32_t b0 = hB1[c0], b1 = hB1[c1];
                mma16816(acc2[nt], c_h[kk], b0, b1);
                mma16816(acc2[nt], c_l[kk], b0, b1);
                b0 = hB2[c0]; b1 = hB2[c1];
                mma16816(acc2[nt], dh, b0, b1);
                mma16816(acc2[nt], dl, b0, b1);
            }
        }
        #pragma unroll
        for (int nt = 0; nt < 2; ++nt) {
            *(float2*)(sGate2 + (16 * w + g) * GS + 8 * nt + 2 * tg) =
                make_float2(acc2[nt][0], acc2[nt][1]);
            *(float2*)(sGate2 + (16 * w + g + 8) * GS + 8 * nt + 2 * tg) =
                make_float2(acc2[nt][2], acc2[nt][3]);
        }
        __syncthreads();

        float2 G[4];
        #pragma unroll
        for (int p = 0; p < 4; ++p)
            G[p] = *(const float2*)(sGate2 + (hC + 64 * p) * GS + bC);
        #pragma unroll
        for (int q = 0; q < 2; ++q) {
            float gi = (q ? G[0].y : G[0].x) + bv[0];
            float gf = (q ? G[1].y : G[1].x) + bv[1];
            float gg = (q ? G[2].y : G[2].x) + bv[2];
            float go = (q ? G[3].y : G[3].x) + bv[3];
            gi = fsig(gi); gf = fsig(gf); go = fsig(go); gg = ftanh(gg);
            const float c = gf * c2_reg[q] + gi * gg;
            sHL[hC * 20 + bC + q] = go * ftanh(c);
        }
        __syncthreads();
    }

    // FC head: out = h2_last @ fc_w^T + fc_b
    for (int idx = tid; idx < 16 * O; idx += 512) {
        int b = idx / O, o = idx - (idx / O) * O;
        float s = fc_b[o];
        #pragma unroll
        for (int h = 0; h < H; ++h)
            s += sHL[h * 20 + b] * fc_w[o * H + h];
        out[(batch0 + b) * O + o] = s;
    }
}

extern "C" void kernel_launch(void* const* d_in, const int* in_sizes, int n_in,
                              void* d_out, int out_size) {
    const float* x     = (const float*)d_in[0];
    const float* w_ih0 = (const float*)d_in[1];
    const float* w_hh0 = (const float*)d_in[2];
    const float* b_ih0 = (const float*)d_in[3];
    const float* b_hh0 = (const float*)d_in[4];
    const float* w_ih1 = (const float*)d_in[5];
    const float* w_hh1 = (const float*)d_in[6];
    const float* b_ih1 = (const float*)d_in[7];
    const float* b_hh1 = (const float*)d_in[8];
    const float* fc_w  = (const float*)d_in[9];
    const float* fc_b  = (const float*)d_in[10];
    float* out = (float*)d_out;

    const int smG1 = 640 * (96 + 8) * 2;    // 133120 B
    const int smR = (1536 + 16384 + 2 * 256 * GS + 64 * 20) * 4 + 256;

    cudaFuncSetAttribute(gemm_pre_mma<88, 96>,
                         cudaFuncAttributeMaxDynamicSharedMemorySize, smG1);
    cudaFuncSetAttribute(lstm_fused,
                         cudaFuncAttributeMaxDynamicSharedMemorySize, smR);

    gemm_pre_mma<88, 96><<<148, 512, smG1>>>(x, w_ih0, b_ih0, b_hh0);
    lstm_fused<<<B / 16, 512, smR>>>(
        w_hh0, w_ih1, w_hh1, b_ih1, b_hh1, fc_w, fc_b, out);
}

// round 13
// speedup vs baseline: 6.5712x; 1.0261x over previous
#include <cuda_runtime.h>
#include <cuda_fp16.h>
#include <cstdint>
#include <math.h>

// MusicRNN: 2-layer LSTM (B=2048, T=256, I=88, H=64) + FC (O=13).
// R12 (on top of R11):
//  - W_hh1 UNSPLIT (single fp16): -16 invariant sWD smem reads and -8 MMAs
//    per thread per step (its 2^-12 operand error matches the h-rounding
//    error already present; predicted final ~1.5e-4 vs 1e-3 gate).
//  - gate smem buffers packed fp16 (u32 = 2 adjacent batches, stride 13):
//    halves gate store/load wavefronts; conflict-free activation reads.
// Structure: gemm1 -> fused 2-layer rec (+FC head).

namespace {
constexpr int B = 2048, T = 256, I = 88, H = 64, O = 13, G4 = 256;
constexpr int NTILES = T * (B / 128);       // 4096 tiles of 128 rows
constexpr int HBS = 24;                      // hB row stride (words)
constexpr int GS2 = 13;                      // packed gate row stride (words)
}

// scratch (static __device__: allocation-free rule)
__device__ __half g_pre1[(size_t)T * B * G4];   // 256 MB: x @ W_ih0^T + bias0

// ---------------- warp-MMA fp16 (baseline PTX, works on .target sm_103) ----
__device__ __forceinline__ void mma16816(float* c, const uint32_t* a,
                                         uint32_t b0, uint32_t b1) {
    asm volatile(
        "mma.sync.aligned.m16n8k16.row.col.f32.f16.f16.f32 "
        "{%0,%1,%2,%3}, {%4,%5,%6,%7}, {%8,%9}, {%0,%1,%2,%3};"
        : "+f"(c[0]), "+f"(c[1]), "+f"(c[2]), "+f"(c[3])
        : "r"(a[0]), "r"(a[1]), "r"(a[2]), "r"(a[3]), "r"(b0), "r"(b1));
}
__device__ __forceinline__ uint32_t ld32h(const __half* p) {
    return *(const uint32_t*)p;
}
__device__ __forceinline__ void split_f16(float v, __half& h, __half& l) {
    h = __float2half_rn(v);
    l = __float2half_rn(v - __half2float(h));
}
__device__ __forceinline__ uint32_t packh(__half a, __half b) {
    return (uint32_t)__half_as_ushort(a) | ((uint32_t)__half_as_ushort(b) << 16);
}
__device__ __forceinline__ uint32_t packf(float a, float b) {
    return packh(__float2half_rn(a), __float2half_rn(b));
}
// HW tanh (sm_75+ baseline PTX). abs err ~5e-4: same order as fp16 rounding.
__device__ __forceinline__ float ftanh(float x) {
    float y; asm("tanh.approx.f32 %0, %1;" : "=f"(y) : "f"(x)); return y;
}
__device__ __forceinline__ float fsig(float x) {
    float y; asm("tanh.approx.f32 %0, %1;" : "=f"(y) : "f"(0.5f * x));
    return fmaf(0.5f, y, 0.5f);
}

// ---------------- pre-GEMM 1: pre1 = x @ W_ih0^T + bias0 (fp16 out) --------
template <int KDATA, int KP>
__global__ void __launch_bounds__(512, 1) gemm_pre_mma(
    const float* __restrict__ src,   // x [B][T][KDATA]
    const float* __restrict__ w,     // [256][KDATA]
    const float* __restrict__ bia, const float* __restrict__ bib)
{
    constexpr int SA = KP + 8;   // row stride in halves
    extern __shared__ __half smh[];
    __half* sWH = smh;                 // [256][SA]
    __half* sWL = sWH + 256 * SA;      // [256][SA]
    __half* sA  = sWL + 256 * SA;      // [128][SA]  x (single fp16)

    const int tid = threadIdx.x;
    for (int i = tid; i < 640 * SA / 2; i += 512)
        ((uint32_t*)smh)[i] = 0u;
    __syncthreads();

    for (int idx = tid; idx < 256 * KDATA; idx += 512) {
        int j = idx / KDATA, k = idx - j * KDATA;
        __half h, l;
        split_f16(w[idx], h, l);
        sWH[j * SA + k] = h;
        sWL[j * SA + k] = l;
    }
    if (tid < 256) {
        __half h, l;
        split_f16(bia[tid] + bib[tid], h, l);
        sWH[tid * SA + KDATA] = h;
        sWL[tid * SA + KDATA] = l;
    }
    if (tid < 128)
        sA[tid * SA + KDATA] = __float2half_rn(1.0f);  // ones col (exact)

    const int lane = tid & 31, wid = tid >> 5;
    const int g = lane >> 2, tg = lane & 3;
    const int wRow = (wid & 3) * 32;
    const int wCol = (wid >> 2) * 64;

    for (int tile = blockIdx.x; tile < NTILES; tile += gridDim.x) {
        const int t = tile >> 4, b0 = (tile & 15) << 7;

        __syncthreads();
        for (int idx = tid; idx < 128 * (KDATA / 2); idx += 512) {
            int m = idx / (KDATA / 2), kp = idx - m * (KDATA / 2);
            const float* rp = src + ((size_t)(b0 + m) * T + t) * KDATA;
            float2 v = *(const float2*)(rp + 2 * kp);
            __half2 hp;
            hp.x = __float2half_rn(v.x);
            hp.y = __float2half_rn(v.y);
            *(__half2*)(sA + m * SA + 2 * kp) = hp;
        }
        __syncthreads();

        float acc[2][8][4] = {};
        #pragma unroll
        for (int kk = 0; kk < KP / 16; ++kk) {
            uint32_t ah[2][4];
            #pragma unroll
            for (int f = 0; f < 2; ++f) {
                const int base = (wRow + f * 16 + g) * SA + kk * 16 + tg * 2;
                ah[f][0] = ld32h(sA + base);
                ah[f][1] = ld32h(sA + base + 8 * SA);
                ah[f][2] = ld32h(sA + base + 8);
                ah[f][3] = ld32h(sA + base + 8 * SA + 8);
            }
            #pragma unroll
            for (int n = 0; n < 8; ++n) {
                const int bbase = (wCol + n * 8 + g) * SA + kk * 16 + tg * 2;
                const uint32_t bh0 = ld32h(sWH + bbase);
                const uint32_t bh1 = ld32h(sWH + bbase + 8);
                const uint32_t bl0 = ld32h(sWL + bbase);
                const uint32_t bl1 = ld32h(sWL + bbase + 8);
                #pragma unroll
                for (int f = 0; f < 2; ++f) {
                    mma16816(acc[f][n], ah[f], bh0, bh1);
                    mma16816(acc[f][n], ah[f], bl0, bl1);
                }
            }
        }

        __half* orow = g_pre1 + ((size_t)t * B + b0) * G4;
        #pragma unroll
        for (int f = 0; f < 2; ++f) {
            const int r0 = wRow + f * 16 + g;
            #pragma unroll
            for (int n = 0; n < 8; ++n) {
                const int col = wCol + n * 8 + tg * 2;
                __stcs((uint32_t*)(orow + (size_t)r0 * G4 + col),
                       packf(acc[f][n][0], acc[f][n][1]));
                __stcs((uint32_t*)(orow + (size_t)(r0 + 8) * G4 + col),
                       packf(acc[f][n][2], acc[f][n][3]));
            }
        }
    }
}

// ---------------- fused 2-layer recurrence (fp16) --------------------------
__global__ void __launch_bounds__(512, 1) lstm_fused(
    const float* __restrict__ w_hh0,  // [256][64]
    const float* __restrict__ w_ih1,  // [256][64]
    const float* __restrict__ w_hh1,  // [256][64]
    const float* __restrict__ bi1,    // [256]
    const float* __restrict__ bh1,    // [256]
    const float* __restrict__ fc_w,   // [O][H]
    const float* __restrict__ fc_b,   // [O]
    float* __restrict__ out)          // [B][O]
{
    extern __shared__ uint32_t smu[];
    uint32_t* hB1 = smu;                       // [32][HBS] h1 fp16 pairs
    uint32_t* hB2 = smu + 768;                 // [32][HBS] h2 fp16 pairs
    uint32_t* sWD = smu + 1536;                // [16 words][512] W_hh1 frags (hi only)
    uint32_t* sG1 = smu + 1536 + 8192;         // [256][GS2] packed fp16 gates1
    uint32_t* sG2 = sG1 + 256 * GS2;           // [256][GS2] packed fp16 gates2
    float* sHL    = (float*)(sG2 + 256 * GS2); // [64][20]

    const int tid = threadIdx.x;
    const int lane = tid & 31, w = tid >> 5;
    const int g = lane >> 2, tg = lane & 3;
    const int batch0 = blockIdx.x * 16;

    for (int i = tid; i < 1536; i += 512) smu[i] = 0u;   // h buffers = 0

    // static A frags: W_hh0 (a), W_ih1 (c) split in regs; W_hh1 (d) hi-only smem
    uint32_t a_h[4][4], a_l[4][4], c_h[4][4], c_l[4][4];
    #pragma unroll
    for (int kk = 0; kk < 4; ++kk) {
        #pragma unroll
        for (int r = 0; r < 4; ++r) {
            const int row = 16 * w + g + (r & 1) * 8;
            const int col = 16 * kk + 2 * tg + (r >> 1) * 8;
            __half h0, l0, h1, l1;
            float2 v = *(const float2*)(w_hh0 + row * 64 + col);
            split_f16(v.x, h0, l0); split_f16(v.y, h1, l1);
            a_h[kk][r] = packh(h0, h1); a_l[kk][r] = packh(l0, l1);
            float2 u = *(const float2*)(w_ih1 + row * 64 + col);
            split_f16(u.x, h0, l0); split_f16(u.y, h1, l1);
            c_h[kk][r] = packh(h0, h1); c_l[kk][r] = packh(l0, l1);
            float2 z = *(const float2*)(w_hh1 + row * 64 + col);
            sWD[(kk * 4 + r) * 512 + tid] =
                packh(__float2half_rn(z.x), __float2half_rn(z.y));
        }
    }

    const int hC = tid & 63;
    const int bC = (tid >> 6) * 2;
    const int gcol = tid >> 6;        // packed gate column (= bC/2)
    float c1_reg[2] = {0.f, 0.f};
    float c2_reg[2] = {0.f, 0.f};
    float bv[4];
    #pragma unroll
    for (int p = 0; p < 4; ++p)
        bv[p] = bi1[p * 64 + hC] + bh1[p * 64 + hC];
    __syncthreads();

    for (int t = 0; t < T; ++t) {
        // prefetch pre1[t] fp16 (overlaps MMA phase)
        const __half* pt = g_pre1 + ((size_t)t * B + batch0) * G4;
        float pv[2][4];
        #pragma unroll
        for (int q = 0; q < 2; ++q)
            #pragma unroll
            for (int p = 0; p < 4; ++p) {
                unsigned short us =
                    __ldcs((const unsigned short*)(pt + (bC + q) * G4 + p * 64 + hC));
                pv[q][p] = __half2float(__ushort_as_half(us));
            }

        float acc1[2][4] = {};   // gates1 rec part
        float acc2[2][4] = {};   // gates2 = Wih1@h1 + Whh1@h2
        // part 1: B = h1[t-1] feeds acc1 (W_hh0 split) and acc2 (W_ih1 split)
        #pragma unroll
        for (int kk = 0; kk < 4; ++kk) {
            #pragma unroll
            for (int nt = 0; nt < 2; ++nt) {
                const int c0 = (8 * kk + tg) * HBS + 8 * nt + g;
                const int c1 = (8 * kk + 4 + tg) * HBS + 8 * nt + g;
                const uint32_t b0 = hB1[c0], b1 = hB1[c1];
                mma16816(acc1[nt], a_h[kk], b0, b1);
                mma16816(acc2[nt], c_h[kk], b0, b1);
                mma16816(acc1[nt], a_l[kk], b0, b1);
                mma16816(acc2[nt], c_l[kk], b0, b1);
            }
        }
        // part 2: B = h2[t-2] feeds acc2 (W_hh1 hi-only from SMEM frag cache)
        #pragma unroll
        for (int kk = 0; kk < 4; ++kk) {
            uint32_t dh[4];
            #pragma unroll
            for (int r = 0; r < 4; ++r)
                dh[r] = sWD[(kk * 4 + r) * 512 + tid];
            #pragma unroll
            for (int nt = 0; nt < 2; ++nt) {
                const int c0 = (8 * kk + tg) * HBS + 8 * nt + g;
                const int c1 = (8 * kk + 4 + tg) * HBS + 8 * nt + g;
                mma16816(acc2[nt], dh, hB2[c0], hB2[c1]);
            }
        }
        // store gates packed fp16: u32 = batches (8nt+2tg, +1) at col 4nt+tg
        #pragma unroll
        for (int nt = 0; nt < 2; ++nt) {
            const int col = 4 * nt + tg;
            sG1[(16 * w + g) * GS2 + col]     = packf(acc1[nt][0], acc1[nt][1]);
            sG1[(16 * w + g + 8) * GS2 + col] = packf(acc1[nt][2], acc1[nt][3]);
            sG2[(16 * w + g) * GS2 + col]     = packf(acc2[nt][0], acc2[nt][1]);
            sG2[(16 * w + g + 8) * GS2 + col] = packf(acc2[nt][2], acc2[nt][3]);
        }
        __syncthreads();   // BAR1: gates visible; hB reads done

        // activation L1: h1[t]
        float2 G[4];
        #pragma unroll
        for (int p = 0; p < 4; ++p) {
            uint32_t u = sG1[(hC + 64 * p) * GS2 + gcol];
            G[p] = __half22float2(*(__half2*)&u);
        }
        #pragma unroll
        for (int q = 0; q < 2; ++q) {
            float gi = (q ? G[0].y : G[0].x) + pv[q][0];
            float gf = (q ? G[1].y : G[1].x) + pv[q][1];
            float gg = (q ? G[2].y : G[2].x) + pv[q][2];
            float go = (q ? G[3].y : G[3].x) + pv[q][3];
            gi = fsig(gi); gf = fsig(gf); go = fsig(go); gg = ftanh(gg);
            const float c = gf * c1_reg[q] + gi * gg;
            c1_reg[q] = c;
            const float hv = go * ftanh(c);
            const int off = ((hC >> 1) * HBS + bC + q) * 2 + (hC & 1);
            ((unsigned short*)hB1)[off] =
                __half_as_ushort(__float2half_rn(hv));
        }
        // activation L2: h2[t-1] (skip at t=0)
        if (t >= 1) {
            #pragma unroll
            for (int p = 0; p < 4; ++p) {
                uint32_t u = sG2[(hC + 64 * p) * GS2 + gcol];
                G[p] = __half22float2(*(__half2*)&u);
            }
            #pragma unroll
            for (int q = 0; q < 2; ++q) {
                float gi = (q ? G[0].y : G[0].x) + bv[0];
                float gf = (q ? G[1].y : G[1].x) + bv[1];
                float gg = (q ? G[2].y : G[2].x) + bv[2];
                float go = (q ? G[3].y : G[3].x) + bv[3];
                gi = fsig(gi); gf = fsig(gf); go = fsig(go); gg = ftanh(gg);
                const float c = gf * c2_reg[q] + gi * gg;
                c2_reg[q] = c;
                const float hv = go * ftanh(c);
                const int off = ((hC >> 1) * HBS + bC + q) * 2 + (hC & 1);
                ((unsigned short*)hB2)[off] =
                    __half_as_ushort(__float2half_rn(hv));
            }
        }
        __syncthreads();   // BAR2: h writes visible for next step
    }

    // epilogue step t=T: gates2[T-1] from h1[T-1], h2[T-2] -> h2[T-1]
    {
        float acc2[2][4] = {};
        #pragma unroll
        for (int kk = 0; kk < 4; ++kk) {
            uint32_t dh[4];
            #pragma unroll
            for (int r = 0; r < 4; ++r)
                dh[r] = sWD[(kk * 4 + r) * 512 + tid];
            #pragma unroll
            for (int nt = 0; nt < 2; ++nt) {
                const int c0 = (8 * kk + tg) * HBS + 8 * nt + g;
                const int c1 = (8 * kk + 4 + tg) * HBS + 8 * nt + g;
                uint32_t b0 = hB1[c0], b1 = hB1[c1];
                mma16816(acc2[nt], c_h[kk], b0, b1);
                mma16816(acc2[nt], c_l[kk], b0, b1);
                mma16816(acc2[nt], dh, hB2[c0], hB2[c1]);
            }
        }
        #pragma unroll
        for (int nt = 0; nt < 2; ++nt) {
            const int col = 4 * nt + tg;
            sG2[(16 * w + g) * GS2 + col]     = packf(acc2[nt][0], acc2[nt][1]);
            sG2[(16 * w + g + 8) * GS2 + col] = packf(acc2[nt][2], acc2[nt][3]);
        }
        __syncthreads();

        float2 G[4];
        #pragma unroll
        for (int p = 0; p < 4; ++p) {
            uint32_t u = sG2[(hC + 64 * p) * GS2 + gcol];
            G[p] = __half22float2(*(__half2*)&u);
        }
        #pragma unroll
        for (int q = 0; q < 2; ++q) {
            float gi = (q ? G[0].y : G[0].x) + bv[0];
            float gf = (q ? G[1].y : G[1].x) + bv[1];
            float gg = (q ? G[2].y : G[2].x) + bv[2];
            float go = (q ? G[3].y : G[3].x) + bv[3];
            gi = fsig(gi); gf = fsig(gf); go = fsig(go); gg = ftanh(gg);
            const float c = gf * c2_reg[q] + gi * gg;
            sHL[hC * 20 + bC + q] = go * ftanh(c);
        }
        __syncthreads();
    }

    // FC head: out = h2_last @ fc_w^T + fc_b
    for (int idx = tid; idx < 16 * O; idx += 512) {
        int b = idx / O, o = idx - (idx / O) * O;
        float s = fc_b[o];
        #pragma unroll
        for (int h = 0; h < H; ++h)
            s += sHL[h * 20 + b] * fc_w[o * H + h];
        out[(batch0 + b) * O + o] = s;
    }
}

extern "C" void kernel_launch(void* const* d_in, const int* in_sizes, int n_in,
                              void* d_out, int out_size) {
    const float* x     = (const float*)d_in[0];
    const float* w_ih0 = (const float*)d_in[1];
    const float* w_hh0 = (const float*)d_in[2];
    const float* b_ih0 = (const float*)d_in[3];
    const float* b_hh0 = (const float*)d_in[4];
    const float* w_ih1 = (const float*)d_in[5];
    const float* w_hh1 = (const float*)d_in[6];
    const float* b_ih1 = (const float*)d_in[7];
    const float* b_hh1 = (const float*)d_in[8];
    const float* fc_w  = (const float*)d_in[9];
    const float* fc_b  = (const float*)d_in[10];
    float* out = (float*)d_out;

    const int smG1 = 640 * (96 + 8) * 2;    // 133120 B
    const int smR = (1536 + 8192 + 2 * 256 * GS2 + 64 * 20) * 4 + 256;

    cudaFuncSetAttribute(gemm_pre_mma<88, 96>,
                         cudaFuncAttributeMaxDynamicSharedMemorySize, smG1);
    cudaFuncSetAttribute(lstm_fused,
                         cudaFuncAttributeMaxDynamicSharedMemorySize, smR);

    gemm_pre_mma<88, 96><<<148, 512, smG1>>>(x, w_ih0, b_ih0, b_hh0);
    lstm_fused<<<B / 16, 512, smR>>>(
        w_hh0, w_ih1, w_hh1, b_ih1, b_hh1, fc_w, fc_b, out);
}